// round 1
// baseline (speedup 1.0000x reference)
#include <cuda_runtime.h>

// Problem constants
#define B_   64
#define T_   512
#define IN_  1024
#define H_   256
#define G4   1024   // 4*H
#define NC_  8

// Scratch (device globals — no allocation allowed)
__device__ float g_xg[B_ * T_ * G4];   // 128 MB: precomputed input gates (B*T, 4H)
__device__ float g_h1[B_ * T_ * H_];   // 32 MB: layer outputs (B, T, H)
__device__ float g_h2[B_ * T_ * H_];

typedef unsigned long long ull;

// ---- packed f32x2 helpers (B300: 3-reg FFMA is half-rate; f32x2 recovers it) ----
__device__ __forceinline__ ull pk(float x, float y) {
    ull r; asm("mov.b64 %0, {%1,%2};" : "=l"(r) : "f"(x), "f"(y)); return r;
}
__device__ __forceinline__ void upk(ull v, float &x, float &y) {
    asm("mov.b64 {%0,%1}, %2;" : "=f"(x), "=f"(y) : "l"(v));
}
__device__ __forceinline__ void ffma2(ull &d, ull a, ull b) {
    asm("fma.rn.f32x2 %0, %1, %2, %0;" : "+l"(d) : "l"(a), "l"(b));
}

// ============================================================================
// GEMM: C[M,N] = A[M,K] @ W[N,K]^T + bias[N]   (all row-major, fp32)
// BM=128, BN=128, BK=16, 256 threads, 8x8 microtile with f32x2 FMAs.
// M=32768, N=1024, K in {1024, 256} -> all tiles exact, no edge handling.
// ============================================================================
#define BM 128
#define BN 128
#define BK 16

__global__ __launch_bounds__(256) void gemm_bias(
    const float* __restrict__ A, const float* __restrict__ W,
    const float* __restrict__ bias, float* __restrict__ C,
    int M, int N, int K)
{
    __shared__ float As[BK][BM];
    __shared__ float Bs[BK][BN];
    int t  = threadIdx.x;
    int m0 = blockIdx.y * BM, n0 = blockIdx.x * BN;
    int tx = t & 15, ty = t >> 4;

    ull acc[8][4];
#pragma unroll
    for (int i = 0; i < 8; i++)
#pragma unroll
        for (int j = 0; j < 4; j++) acc[i][j] = 0ull;

    int lr = t >> 2;        // 0..63
    int lc = (t & 3) * 4;   // 0,4,8,12

    const float* Ap = A + (ull)(m0 + lr) * K + lc;
    const float* Wp = W + (ull)(n0 + lr) * K + lc;

    for (int k0 = 0; k0 < K; k0 += BK) {
#pragma unroll
        for (int it = 0; it < 2; it++) {
            float4 va = *(const float4*)(Ap + (ull)(it * 64) * K + k0);
            float4 vw = *(const float4*)(Wp + (ull)(it * 64) * K + k0);
            int row = lr + it * 64;
            As[lc + 0][row] = va.x; As[lc + 1][row] = va.y;
            As[lc + 2][row] = va.z; As[lc + 3][row] = va.w;
            Bs[lc + 0][row] = vw.x; Bs[lc + 1][row] = vw.y;
            Bs[lc + 2][row] = vw.z; Bs[lc + 3][row] = vw.w;
        }
        __syncthreads();
#pragma unroll
        for (int k = 0; k < BK; k++) {
            float4 a0 = *(const float4*)&As[k][ty * 8];
            float4 a1 = *(const float4*)&As[k][ty * 8 + 4];
            float4 b0 = *(const float4*)&Bs[k][tx * 8];
            float4 b1 = *(const float4*)&Bs[k][tx * 8 + 4];
            ull bb[4] = { pk(b0.x, b0.y), pk(b0.z, b0.w),
                          pk(b1.x, b1.y), pk(b1.z, b1.w) };
            float av[8] = { a0.x, a0.y, a0.z, a0.w, a1.x, a1.y, a1.z, a1.w };
#pragma unroll
            for (int i = 0; i < 8; i++) {
                ull aa = pk(av[i], av[i]);
#pragma unroll
                for (int j = 0; j < 4; j++) ffma2(acc[i][j], aa, bb[j]);
            }
        }
        __syncthreads();
    }

#pragma unroll
    for (int i = 0; i < 8; i++) {
        int m = m0 + ty * 8 + i;
        float o[8];
#pragma unroll
        for (int j = 0; j < 4; j++) upk(acc[i][j], o[2 * j], o[2 * j + 1]);
#pragma unroll
        for (int j = 0; j < 8; j++) o[j] += bias[n0 + tx * 8 + j];
        *(float4*)&C[(ull)m * N + n0 + tx * 8]     = make_float4(o[0], o[1], o[2], o[3]);
        *(float4*)&C[(ull)m * N + n0 + tx * 8 + 4] = make_float4(o[4], o[5], o[6], o[7]);
    }
}

// ============================================================================
// LSTM recurrence for one layer. One block = 2 batch elements (amortize Whh
// L2 reads). 512 threads: phase 1 each thread does 2 gate rows x 2 batches
// (4 dot products of length 256, f32x2-packed over k); phase 2 gate update.
// Whh: (4H, H) row-major. xg: (B*T, 4H). hout: (B, T, H).
// ============================================================================
__global__ __launch_bounds__(512) void lstm_recur(
    const float* __restrict__ xg, const float* __restrict__ Whh,
    float* __restrict__ hout)
{
    __shared__ float hA[H_], hB[H_], cA[H_], cB[H_];
    __shared__ float gA[G4], gB[G4];
    int t = threadIdx.x;
    int b0 = blockIdx.x * 2, b1 = b0 + 1;
    if (t < H_) { hA[t] = 0.f; hB[t] = 0.f; cA[t] = 0.f; cB[t] = 0.f; }
    __syncthreads();

    int r0 = t, r1 = t + 512;
    const float* w0p = Whh + r0 * H_;
    const float* w1p = Whh + r1 * H_;
    const float* xg0 = xg + (ull)b0 * T_ * G4;
    const float* xg1 = xg + (ull)b1 * T_ * G4;

    for (int ts = 0; ts < T_; ts++) {
        ull aA0 = 0, aB0 = 0, aA1 = 0, aB1 = 0;
#pragma unroll 8
        for (int k = 0; k < H_; k += 4) {
            float4 w0 = *(const float4*)(w0p + k);
            float4 w1 = *(const float4*)(w1p + k);
            float4 ha = *(const float4*)(hA + k);
            float4 hb = *(const float4*)(hB + k);
            ull ha01 = pk(ha.x, ha.y), ha23 = pk(ha.z, ha.w);
            ull hb01 = pk(hb.x, hb.y), hb23 = pk(hb.z, hb.w);
            ull w001 = pk(w0.x, w0.y), w023 = pk(w0.z, w0.w);
            ull w101 = pk(w1.x, w1.y), w123 = pk(w1.z, w1.w);
            ffma2(aA0, w001, ha01); ffma2(aA0, w023, ha23);
            ffma2(aB0, w001, hb01); ffma2(aB0, w023, hb23);
            ffma2(aA1, w101, ha01); ffma2(aA1, w123, ha23);
            ffma2(aB1, w101, hb01); ffma2(aB1, w123, hb23);
        }
        float x1, x2;
        upk(aA0, x1, x2); gA[r0] = x1 + x2 + xg0[ts * G4 + r0];
        upk(aB0, x1, x2); gB[r0] = x1 + x2 + xg1[ts * G4 + r0];
        upk(aA1, x1, x2); gA[r1] = x1 + x2 + xg0[ts * G4 + r1];
        upk(aB1, x1, x2); gB[r1] = x1 + x2 + xg1[ts * G4 + r1];
        __syncthreads();

        // phase 2: 512 threads = 256 hidden units x 2 batches
        {
            int j   = t & (H_ - 1);
            int sel = t >> 8;
            float* g  = sel ? gB : gA;
            float* hs = sel ? hB : hA;
            float* cs = sel ? cB : cA;
            int bb    = sel ? b1 : b0;
            float iv = 1.f / (1.f + __expf(-g[j]));
            float fv = 1.f / (1.f + __expf(-g[H_ + j]));
            float gv = tanhf(g[2 * H_ + j]);
            float ov = 1.f / (1.f + __expf(-g[3 * H_ + j]));
            float c  = fv * cs[j] + iv * gv;
            float h  = ov * tanhf(c);
            cs[j] = c; hs[j] = h;
            hout[((ull)bb * T_ + ts) * H_ + j] = h;
        }
        __syncthreads();
    }
}

// ============================================================================
// FC head: out[b] = relu(h_last[b] @ W1^T + bfc1) @ W2^T + bfc2
// ============================================================================
__global__ __launch_bounds__(128) void fc_head(
    const float* __restrict__ hall, const float* __restrict__ W1,
    const float* __restrict__ b1,   const float* __restrict__ W2,
    const float* __restrict__ b2,   float* __restrict__ out)
{
    __shared__ float hl[H_];
    __shared__ float z[128];
    int b = blockIdx.x, t = threadIdx.x;
    hl[t]       = hall[((ull)b * T_ + (T_ - 1)) * H_ + t];
    hl[t + 128] = hall[((ull)b * T_ + (T_ - 1)) * H_ + t + 128];
    __syncthreads();
    float acc = b1[t];
    const float* w = W1 + t * H_;
#pragma unroll 8
    for (int k = 0; k < H_; k++) acc += w[k] * hl[k];
    z[t] = fmaxf(acc, 0.f);
    __syncthreads();
    if (t < NC_) {
        float a2 = b2[t];
        const float* w2 = W2 + t * 128;
#pragma unroll 8
        for (int k = 0; k < 128; k++) a2 += w2[k] * z[k];
        out[b * NC_ + t] = a2;
    }
}

// ============================================================================
extern "C" void kernel_launch(void* const* d_in, const int* in_sizes, int n_in,
                              void* d_out, int out_size)
{
    const float* x    = (const float*)d_in[0];
    const float* Wih0 = (const float*)d_in[1];
    const float* Whh0 = (const float*)d_in[2];
    const float* b0   = (const float*)d_in[3];
    const float* Wih1 = (const float*)d_in[4];
    const float* Whh1 = (const float*)d_in[5];
    const float* b1   = (const float*)d_in[6];
    const float* Wih2 = (const float*)d_in[7];
    const float* Whh2 = (const float*)d_in[8];
    const float* b2   = (const float*)d_in[9];
    const float* W1   = (const float*)d_in[10];
    const float* bfc1 = (const float*)d_in[11];
    const float* W2   = (const float*)d_in[12];
    const float* bfc2 = (const float*)d_in[13];
    float* out = (float*)d_out;

    float *xg, *h1, *h2;
    cudaGetSymbolAddress((void**)&xg, g_xg);
    cudaGetSymbolAddress((void**)&h1, g_h1);
    cudaGetSymbolAddress((void**)&h2, g_h2);

    dim3 blk(256);
    dim3 grd(G4 / BN, (B_ * T_) / BM);   // (8, 256)

    // layer 0
    gemm_bias<<<grd, blk>>>(x, Wih0, b0, xg, B_ * T_, G4, IN_);
    lstm_recur<<<B_ / 2, 512>>>(xg, Whh0, h1);
    // layer 1
    gemm_bias<<<grd, blk>>>(h1, Wih1, b1, xg, B_ * T_, G4, H_);
    lstm_recur<<<B_ / 2, 512>>>(xg, Whh1, h2);
    // layer 2
    gemm_bias<<<grd, blk>>>(h2, Wih2, b2, xg, B_ * T_, G4, H_);
    lstm_recur<<<B_ / 2, 512>>>(xg, Whh2, h1);
    // head
    fc_head<<<B_, 128>>>(h1, W1, bfc1, W2, bfc2, out);
}

// round 3
// speedup vs baseline: 5.3019x; 5.3019x over previous
#include <cuda_runtime.h>
#include <cstdint>

// Problem constants
#define B_   64
#define T_   512
#define IN_  1024
#define H_   256
#define G4   1024   // 4*H
#define NC_  8

// Recurrence config
#define CLUSTER   8            // CTAs per cluster
#define NB        4            // batches per cluster
#define NCL       (B_ / NB)    // 16 clusters -> 128 CTAs
#define THR       256          // threads per recurrence CTA
#define WPITCH    130          // padded floats per k-row of Wsh (bank-conflict-free)

// Scratch (device globals — no allocation allowed)
__device__ float g_xg[B_ * T_ * G4];   // 128 MB: precomputed input gates (B*T, 4H)
__device__ float g_h1[B_ * T_ * H_];
__device__ float g_h2[B_ * T_ * H_];

typedef unsigned long long ull;

// ---- packed f32x2 helpers (B300: 3-reg FFMA is half-rate; f32x2 recovers it) ----
__device__ __forceinline__ ull pk(float x, float y) {
    ull r; asm("mov.b64 %0, {%1,%2};" : "=l"(r) : "f"(x), "f"(y)); return r;
}
__device__ __forceinline__ void upk(ull v, float &x, float &y) {
    asm("mov.b64 {%0,%1}, %2;" : "=f"(x), "=f"(y) : "l"(v));
}
__device__ __forceinline__ void ffma2(ull &d, ull a, ull b) {
    asm("fma.rn.f32x2 %0, %1, %2, %0;" : "+l"(d) : "l"(a), "l"(b));
}
__device__ __forceinline__ uint32_t smem_u32(const void* p) {
    uint32_t a;
    asm("{ .reg .u64 t; cvta.to.shared.u64 t, %1; cvt.u32.u64 %0, t; }" : "=r"(a) : "l"(p));
    return a;
}

// ============================================================================
// GEMM: C[M,N] = A[M,K] @ W[N,K]^T + bias[N]   (row-major fp32) — unchanged R1
// ============================================================================
#define BM 128
#define BN 128
#define BK 16

__global__ __launch_bounds__(256) void gemm_bias(
    const float* __restrict__ A, const float* __restrict__ W,
    const float* __restrict__ bias, float* __restrict__ C,
    int M, int N, int K)
{
    __shared__ float As[BK][BM];
    __shared__ float Bs[BK][BN];
    int t  = threadIdx.x;
    int m0 = blockIdx.y * BM, n0 = blockIdx.x * BN;
    int tx = t & 15, ty = t >> 4;

    ull acc[8][4];
#pragma unroll
    for (int i = 0; i < 8; i++)
#pragma unroll
        for (int j = 0; j < 4; j++) acc[i][j] = 0ull;

    int lr = t >> 2;
    int lc = (t & 3) * 4;

    const float* Ap = A + (ull)(m0 + lr) * K + lc;
    const float* Wp = W + (ull)(n0 + lr) * K + lc;

    for (int k0 = 0; k0 < K; k0 += BK) {
#pragma unroll
        for (int it = 0; it < 2; it++) {
            float4 va = *(const float4*)(Ap + (ull)(it * 64) * K + k0);
            float4 vw = *(const float4*)(Wp + (ull)(it * 64) * K + k0);
            int row = lr + it * 64;
            As[lc + 0][row] = va.x; As[lc + 1][row] = va.y;
            As[lc + 2][row] = va.z; As[lc + 3][row] = va.w;
            Bs[lc + 0][row] = vw.x; Bs[lc + 1][row] = vw.y;
            Bs[lc + 2][row] = vw.z; Bs[lc + 3][row] = vw.w;
        }
        __syncthreads();
#pragma unroll
        for (int k = 0; k < BK; k++) {
            float4 a0 = *(const float4*)&As[k][ty * 8];
            float4 a1 = *(const float4*)&As[k][ty * 8 + 4];
            float4 b0 = *(const float4*)&Bs[k][tx * 8];
            float4 b1 = *(const float4*)&Bs[k][tx * 8 + 4];
            ull bb[4] = { pk(b0.x, b0.y), pk(b0.z, b0.w),
                          pk(b1.x, b1.y), pk(b1.z, b1.w) };
            float av[8] = { a0.x, a0.y, a0.z, a0.w, a1.x, a1.y, a1.z, a1.w };
#pragma unroll
            for (int i = 0; i < 8; i++) {
                ull aa = pk(av[i], av[i]);
#pragma unroll
                for (int j = 0; j < 4; j++) ffma2(acc[i][j], aa, bb[j]);
            }
        }
        __syncthreads();
    }

#pragma unroll
    for (int i = 0; i < 8; i++) {
        int m = m0 + ty * 8 + i;
        float o[8];
#pragma unroll
        for (int j = 0; j < 4; j++) upk(acc[i][j], o[2 * j], o[2 * j + 1]);
#pragma unroll
        for (int j = 0; j < 8; j++) o[j] += bias[n0 + tx * 8 + j];
        *(float4*)&C[(ull)m * N + n0 + tx * 8]     = make_float4(o[0], o[1], o[2], o[3]);
        *(float4*)&C[(ull)m * N + n0 + tx * 8 + 4] = make_float4(o[4], o[5], o[6], o[7]);
    }
}

// ============================================================================
// Cluster LSTM recurrence.
// 16 clusters x 8 CTAs x 256 thr. Cluster cl owns batches [4cl,4cl+4).
// CTA rank c owns hidden units j in [32c,32c+32) => gate rows {g*256+32c+u}.
// Weights cached in SMEM (k-major, pitch 130, conflict-free), loaded once.
// Per step: phase1 partial dots (thread=(rowpair, kseg)); phase2 gate update
// (thread=(unit,batch), c in registers), h broadcast to peers via DSMEM,
// one barrier.cluster per step.
//
// SMEM layout (dynamic):
//   Wsh  : float[256][WPITCH]         133120 B   Wsh[k][ri], ri = g*32+u
//   hsp  : float[2][256][NB]            8192 B   h double buffer, [k][batch]
//   pscr : ull  [NB][4][64]             8192 B   partials [b][kseg][rowpair]
// ============================================================================
#define SMEM_W    0
#define SMEM_H    (256 * WPITCH)            // float offset
#define SMEM_P    (SMEM_H + 2 * 256 * NB)   // float offset
#define SMEM_RECUR_BYTES ((SMEM_P + NB * 4 * 64 * 2) * 4)

extern __shared__ float smr[];

__global__ __launch_bounds__(THR, 1) __cluster_dims__(CLUSTER, 1, 1)
void lstm_recur_cl(const float* __restrict__ xg, const float* __restrict__ Whh,
                   float* __restrict__ hout)
{
    float* Wsh  = smr;
    float* hsp  = smr + SMEM_H;
    float* pscr = smr + SMEM_P;

    int t = threadIdx.x;
    uint32_t rank;
    asm("mov.u32 %0, %%cluster_ctarank;" : "=r"(rank));
    int b0 = (blockIdx.x / CLUSTER) * NB;

    // ---- load + transpose weight slice: Wsh[k][ri] = Whh[256*g + 32*rank + u][k]
    for (int idx = t; idx < 128 * 64; idx += THR) {
        int ri = idx >> 6;            // 0..127, warp-lanes share ri ranges
        int k4 = idx & 63;            // lanes consecutive -> coalesced LDG.128
        int g = ri >> 5, u = ri & 31;
        int row = 256 * g + 32 * (int)rank + u;
        float4 v = *(const float4*)(Whh + (ull)row * H_ + 4 * k4);
        int k = 4 * k4;
        Wsh[(k + 0) * WPITCH + ri] = v.x;
        Wsh[(k + 1) * WPITCH + ri] = v.y;
        Wsh[(k + 2) * WPITCH + ri] = v.z;
        Wsh[(k + 3) * WPITCH + ri] = v.w;
    }
    // zero both h buffers
    for (int i = t; i < 2 * 256 * NB; i += THR) hsp[i] = 0.f;
    __syncthreads();
    // all CTAs initialized before anyone's remote h writes can land
    asm volatile("barrier.cluster.arrive.aligned;" ::: "memory");
    asm volatile("barrier.cluster.wait.aligned;" ::: "memory");

    int rp = t & 63;      // rowpair: rows ri=2rp, 2rp+1
    int ks = t >> 6;      // k-segment of 64
    // phase2 identity (threads 0..127): unit u2, batch b2
    int u2 = t & 31, b2 = (t >> 5) & 3;
    float c_reg = 0.f;
    int jown = 32 * (int)rank + u2;

    // hoist mapa: remote addr of hsp[0][jown][b2] in each peer CTA
    uint32_t raj[CLUSTER];
    {
        uint32_t loc = smem_u32(hsp + ((0 * 256 + jown) * NB + b2));
#pragma unroll
        for (int r = 0; r < CLUSTER; r++)
            asm("mapa.shared::cluster.u32 %0, %1, %2;" : "=r"(raj[r]) : "r"(loc), "r"(r));
    }

    ull* ps = (ull*)pscr;
    int buf = 0;
    for (int ts = 0; ts < T_; ts++) {
        // prefetch xg for phase2 (hidden behind phase1)
        float xgv0, xgv1, xgv2, xgv3;
        if (t < 128) {
            const float* xp = xg + ((ull)(b0 + b2) * T_ + ts) * G4 + 32 * rank + u2;
            xgv0 = xp[0]; xgv1 = xp[256]; xgv2 = xp[512]; xgv3 = xp[768];
        }
        // ---- phase 1: partial dot products over kseg
        const float* hb = hsp + (buf * 256 + 64 * ks) * NB;
        const float* wk = Wsh + (64 * ks) * WPITCH + 2 * rp;
        ull a0 = 0, a1 = 0, a2 = 0, a3 = 0;
#pragma unroll 4
        for (int k = 0; k < 64; k++) {
            ull w = *(const ull*)wk;               // (w[ri=2rp], w[2rp+1])
            float4 h4 = *(const float4*)hb;        // broadcast: h of 4 batches
            wk += WPITCH; hb += NB;
            ffma2(a0, w, pk(h4.x, h4.x));
            ffma2(a1, w, pk(h4.y, h4.y));
            ffma2(a2, w, pk(h4.z, h4.z));
            ffma2(a3, w, pk(h4.w, h4.w));
        }
        ps[(0 * 4 + ks) * 64 + rp] = a0;
        ps[(1 * 4 + ks) * 64 + rp] = a1;
        ps[(2 * 4 + ks) * 64 + rp] = a2;
        ps[(3 * 4 + ks) * 64 + rp] = a3;
        __syncthreads();

        // ---- phase 2: reduce partials, gate update, broadcast h
        if (t < 128) {
            const float* pf = pscr;   // float view: [b][ks][128 ri]
            float gv[4];
#pragma unroll
            for (int g = 0; g < 4; g++) {
                int ri = g * 32 + u2;
                float s = (g == 0) ? xgv0 : (g == 1) ? xgv1 : (g == 2) ? xgv2 : xgv3;
#pragma unroll
                for (int s4 = 0; s4 < 4; s4++)
                    s += pf[(b2 * 4 + s4) * 128 + ri];
                gv[g] = s;
            }
            float iv = 1.f / (1.f + __expf(-gv[0]));
            float fv = 1.f / (1.f + __expf(-gv[1]));
            float gg = tanhf(gv[2]);
            float ov = 1.f / (1.f + __expf(-gv[3]));
            c_reg = fv * c_reg + iv * gg;
            float h = ov * tanhf(c_reg);
            hout[((ull)(b0 + b2) * T_ + ts) * H_ + jown] = h;
            // write h into next buffer of every CTA in the cluster
            uint32_t delta = (uint32_t)((buf ^ 1) * 256 * NB * 4);
#pragma unroll
            for (int r = 0; r < CLUSTER; r++)
                asm volatile("st.shared::cluster.f32 [%0], %1;"
                             :: "r"(raj[r] + delta), "f"(h));
        }
        buf ^= 1;
        asm volatile("barrier.cluster.arrive.aligned;" ::: "memory");
        asm volatile("barrier.cluster.wait.aligned;" ::: "memory");
    }
}

// ============================================================================
// FC head — unchanged R1
// ============================================================================
__global__ __launch_bounds__(128) void fc_head(
    const float* __restrict__ hall, const float* __restrict__ W1,
    const float* __restrict__ b1,   const float* __restrict__ W2,
    const float* __restrict__ b2,   float* __restrict__ out)
{
    __shared__ float hl[H_];
    __shared__ float z[128];
    int b = blockIdx.x, t = threadIdx.x;
    hl[t]       = hall[((ull)b * T_ + (T_ - 1)) * H_ + t];
    hl[t + 128] = hall[((ull)b * T_ + (T_ - 1)) * H_ + t + 128];
    __syncthreads();
    float acc = b1[t];
    const float* w = W1 + t * H_;
#pragma unroll 8
    for (int k = 0; k < H_; k++) acc += w[k] * hl[k];
    z[t] = fmaxf(acc, 0.f);
    __syncthreads();
    if (t < NC_) {
        float a2 = b2[t];
        const float* w2 = W2 + t * 128;
#pragma unroll 8
        for (int k = 0; k < 128; k++) a2 += w2[k] * z[k];
        out[b * NC_ + t] = a2;
    }
}

// ============================================================================
extern "C" void kernel_launch(void* const* d_in, const int* in_sizes, int n_in,
                              void* d_out, int out_size)
{
    const float* x    = (const float*)d_in[0];
    const float* Wih0 = (const float*)d_in[1];
    const float* Whh0 = (const float*)d_in[2];
    const float* b0   = (const float*)d_in[3];
    const float* Wih1 = (const float*)d_in[4];
    const float* Whh1 = (const float*)d_in[5];
    const float* b1   = (const float*)d_in[6];
    const float* Wih2 = (const float*)d_in[7];
    const float* Whh2 = (const float*)d_in[8];
    const float* b2   = (const float*)d_in[9];
    const float* W1   = (const float*)d_in[10];
    const float* bfc1 = (const float*)d_in[11];
    const float* W2   = (const float*)d_in[12];
    const float* bfc2 = (const float*)d_in[13];
    float* out = (float*)d_out;

    float *xg, *h1, *h2;
    cudaGetSymbolAddress((void**)&xg, g_xg);
    cudaGetSymbolAddress((void**)&h1, g_h1);
    cudaGetSymbolAddress((void**)&h2, g_h2);

    cudaFuncSetAttribute(lstm_recur_cl,
                         cudaFuncAttributeMaxDynamicSharedMemorySize,
                         SMEM_RECUR_BYTES);

    dim3 blk(256);
    dim3 grd(G4 / BN, (B_ * T_) / BM);   // (8, 256)
    int rgrid = NCL * CLUSTER;           // 128 CTAs

    // layer 0
    gemm_bias<<<grd, blk>>>(x, Wih0, b0, xg, B_ * T_, G4, IN_);
    lstm_recur_cl<<<rgrid, THR, SMEM_RECUR_BYTES>>>(xg, Whh0, h1);
    // layer 1
    gemm_bias<<<grd, blk>>>(h1, Wih1, b1, xg, B_ * T_, G4, H_);
    lstm_recur_cl<<<rgrid, THR, SMEM_RECUR_BYTES>>>(xg, Whh1, h2);
    // layer 2
    gemm_bias<<<grd, blk>>>(h2, Wih2, b2, xg, B_ * T_, G4, H_);
    lstm_recur_cl<<<rgrid, THR, SMEM_RECUR_BYTES>>>(xg, Whh2, h1);
    // head
    fc_head<<<B_, 128>>>(h1, W1, bfc1, W2, bfc2, out);
}

// round 4
// speedup vs baseline: 7.1282x; 1.3445x over previous
#include <cuda_runtime.h>
#include <cstdint>

// Problem constants
#define B_   64
#define T_   512
#define IN_  1024
#define H_   256
#define G4   1024   // 4*H
#define NC_  8

// Recurrence config
#define CLUSTER   8            // CTAs per cluster
#define NB        4            // batches per cluster
#define NCL       (B_ / NB)    // 16 clusters -> 128 CTAs
#define THR       512          // threads per recurrence CTA

// Scratch (device globals — no allocation allowed)
__device__ float g_xg[B_ * T_ * G4];   // 128 MB: precomputed input gates (B*T, 4H)
__device__ float g_h1[B_ * T_ * H_];
__device__ float g_h2[B_ * T_ * H_];

typedef unsigned long long ull;

// ---- packed f32x2 helpers ----
__device__ __forceinline__ ull pk(float x, float y) {
    ull r; asm("mov.b64 %0, {%1,%2};" : "=l"(r) : "f"(x), "f"(y)); return r;
}
__device__ __forceinline__ void upk(ull v, float &x, float &y) {
    asm("mov.b64 {%0,%1}, %2;" : "=f"(x), "=f"(y) : "l"(v));
}
__device__ __forceinline__ void ffma2(ull &d, ull a, ull b) {
    asm("fma.rn.f32x2 %0, %1, %2, %0;" : "+l"(d) : "l"(a), "l"(b));
}
__device__ __forceinline__ uint32_t smem_u32(const void* p) {
    uint32_t a;
    asm("{ .reg .u64 t; cvta.to.shared.u64 t, %1; cvt.u32.u64 %0, t; }" : "=r"(a) : "l"(p));
    return a;
}
__device__ __forceinline__ float sigm(float x) { return 1.f / (1.f + __expf(-x)); }
__device__ __forceinline__ float tanh_fast(float x) {
    return 1.f - 2.f / (__expf(2.f * x) + 1.f);
}

// ============================================================================
// GEMM: C[M,N] = A[M,K] @ W[N,K]^T + bias[N]   (row-major fp32) — unchanged
// ============================================================================
#define BM 128
#define BN 128
#define BK 16

__global__ __launch_bounds__(256) void gemm_bias(
    const float* __restrict__ A, const float* __restrict__ W,
    const float* __restrict__ bias, float* __restrict__ C,
    int M, int N, int K)
{
    __shared__ float As[BK][BM];
    __shared__ float Bs[BK][BN];
    int t  = threadIdx.x;
    int m0 = blockIdx.y * BM, n0 = blockIdx.x * BN;
    int tx = t & 15, ty = t >> 4;

    ull acc[8][4];
#pragma unroll
    for (int i = 0; i < 8; i++)
#pragma unroll
        for (int j = 0; j < 4; j++) acc[i][j] = 0ull;

    int lr = t >> 2;
    int lc = (t & 3) * 4;

    const float* Ap = A + (ull)(m0 + lr) * K + lc;
    const float* Wp = W + (ull)(n0 + lr) * K + lc;

    for (int k0 = 0; k0 < K; k0 += BK) {
#pragma unroll
        for (int it = 0; it < 2; it++) {
            float4 va = *(const float4*)(Ap + (ull)(it * 64) * K + k0);
            float4 vw = *(const float4*)(Wp + (ull)(it * 64) * K + k0);
            int row = lr + it * 64;
            As[lc + 0][row] = va.x; As[lc + 1][row] = va.y;
            As[lc + 2][row] = va.z; As[lc + 3][row] = va.w;
            Bs[lc + 0][row] = vw.x; Bs[lc + 1][row] = vw.y;
            Bs[lc + 2][row] = vw.z; Bs[lc + 3][row] = vw.w;
        }
        __syncthreads();
#pragma unroll
        for (int k = 0; k < BK; k++) {
            float4 a0 = *(const float4*)&As[k][ty * 8];
            float4 a1 = *(const float4*)&As[k][ty * 8 + 4];
            float4 b0 = *(const float4*)&Bs[k][tx * 8];
            float4 b1 = *(const float4*)&Bs[k][tx * 8 + 4];
            ull bb[4] = { pk(b0.x, b0.y), pk(b0.z, b0.w),
                          pk(b1.x, b1.y), pk(b1.z, b1.w) };
            float av[8] = { a0.x, a0.y, a0.z, a0.w, a1.x, a1.y, a1.z, a1.w };
#pragma unroll
            for (int i = 0; i < 8; i++) {
                ull aa = pk(av[i], av[i]);
#pragma unroll
                for (int j = 0; j < 4; j++) ffma2(acc[i][j], aa, bb[j]);
            }
        }
        __syncthreads();
    }

#pragma unroll
    for (int i = 0; i < 8; i++) {
        int m = m0 + ty * 8 + i;
        float o[8];
#pragma unroll
        for (int j = 0; j < 4; j++) upk(acc[i][j], o[2 * j], o[2 * j + 1]);
#pragma unroll
        for (int j = 0; j < 8; j++) o[j] += bias[n0 + tx * 8 + j];
        *(float4*)&C[(ull)m * N + n0 + tx * 8]     = make_float4(o[0], o[1], o[2], o[3]);
        *(float4*)&C[(ull)m * N + n0 + tx * 8 + 4] = make_float4(o[4], o[5], o[6], o[7]);
    }
}

// ============================================================================
// Cluster LSTM recurrence, weights in REGISTERS.
// 16 clusters x 8 CTAs x 512 thr. Cluster owns 4 batches; CTA rank owns 32
// hidden units (gate rows {g*256+32*rank+u}).
// Thread (rp = t&63, ks = t>>6): gate rows ri=2rp,2rp+1, k-seg [32ks,32ks+32).
// Weights: 32 reg-pairs per thread, loaded once from GMEM.
// Inner loop pairs over k: acc(row,b) += (w_k,w_k+1)*(h_k,h_k+1) — no MOVs.
// h stored batch-major in SMEM so (h_k,h_k+1) is a natural LDS.128 half.
// Per step: phase1 partials -> SMEM; sync; phase2 (128 thr) reduce + gates,
// broadcast h via DSMEM; cluster arrive; prefetch next xg; cluster wait.
// ============================================================================
__global__ __launch_bounds__(THR, 1) __cluster_dims__(CLUSTER, 1, 1)
void lstm_recur_cl(const float* __restrict__ xg, const float* __restrict__ Whh,
                   float* __restrict__ hout)
{
    __shared__ float hsp[2][NB][H_];       // 8 KB, [parity][batch][k]
    __shared__ float pscr[NB][8][128];     // 16 KB, [batch][kseg][ri]

    int t = threadIdx.x;
    uint32_t rank;
    asm("mov.u32 %0, %%cluster_ctarank;" : "=r"(rank));
    int b0 = (blockIdx.x / CLUSTER) * NB;

    int rp = t & 63;          // row pair: ri0=2rp, ri1=2rp+1
    int ks = t >> 6;          // k-segment of 32

    // ---- load weight slice into registers (one time) ----
    // ri -> global row: 256*(ri>>5) + 32*rank + (ri&31); ri0=2rp even so both
    // rows of the pair share the same gate group.
    ull w0[16], w1[16];
    {
        int g = rp >> 4;
        int u = (2 * rp) & 31;
        const float* p0 = Whh + (ull)(256 * g + 32 * (int)rank + u) * H_ + 32 * ks;
        const float* p1 = p0 + H_;
#pragma unroll
        for (int j = 0; j < 16; j++) {
            w0[j] = *(const ull*)(p0 + 2 * j);
            w1[j] = *(const ull*)(p1 + 2 * j);
        }
    }
    // zero h buffers
    for (int i = t; i < 2 * NB * H_; i += THR) ((float*)hsp)[i] = 0.f;
    __syncthreads();
    asm volatile("barrier.cluster.arrive.aligned;" ::: "memory");
    asm volatile("barrier.cluster.wait.aligned;" ::: "memory");

    // phase-2 identity (threads 0..127): unit u2, batch b2
    int u2 = t & 31, b2 = (t >> 5) & 3;
    float c_reg = 0.f;
    int jown = 32 * (int)rank + u2;

    // hoisted mapa: remote addr of hsp[0][b2][jown] in each peer CTA
    uint32_t raj[CLUSTER];
    {
        uint32_t loc = smem_u32(&hsp[0][b2][jown]);
#pragma unroll
        for (int r = 0; r < CLUSTER; r++)
            asm("mapa.shared::cluster.u32 %0, %1, %2;" : "=r"(raj[r]) : "r"(loc), "r"(r));
    }

    const float* xbase = xg + (ull)(b0 + b2) * T_ * G4 + jown;
    // prefetch xg for ts=0
    float xc0, xc1, xc2, xc3;
    if (t < 128) {
        xc0 = xbase[0]; xc1 = xbase[256]; xc2 = xbase[512]; xc3 = xbase[768];
    }

    int p = 0;
    for (int ts = 0; ts < T_; ts++) {
        // ---- phase 1: partial dots over this thread's 32-k segment
        ull a00 = 0, a01 = 0, a02 = 0, a03 = 0;   // row0 x batch
        ull a10 = 0, a11 = 0, a12 = 0, a13 = 0;   // row1 x batch
        const float* hseg = &hsp[p][0][32 * ks];
#pragma unroll
        for (int j2 = 0; j2 < 8; j2++) {
            longlong2 hb0 = *(const longlong2*)(hseg + 0 * H_ + 4 * j2);
            longlong2 hb1 = *(const longlong2*)(hseg + 1 * H_ + 4 * j2);
            longlong2 hb2 = *(const longlong2*)(hseg + 2 * H_ + 4 * j2);
            longlong2 hb3 = *(const longlong2*)(hseg + 3 * H_ + 4 * j2);
            ull wa0 = w0[2 * j2], wb0 = w0[2 * j2 + 1];
            ull wa1 = w1[2 * j2], wb1 = w1[2 * j2 + 1];
            ffma2(a00, wa0, (ull)hb0.x); ffma2(a00, wb0, (ull)hb0.y);
            ffma2(a01, wa0, (ull)hb1.x); ffma2(a01, wb0, (ull)hb1.y);
            ffma2(a02, wa0, (ull)hb2.x); ffma2(a02, wb0, (ull)hb2.y);
            ffma2(a03, wa0, (ull)hb3.x); ffma2(a03, wb0, (ull)hb3.y);
            ffma2(a10, wa1, (ull)hb0.x); ffma2(a10, wb1, (ull)hb0.y);
            ffma2(a11, wa1, (ull)hb1.x); ffma2(a11, wb1, (ull)hb1.y);
            ffma2(a12, wa1, (ull)hb2.x); ffma2(a12, wb1, (ull)hb2.y);
            ffma2(a13, wa1, (ull)hb3.x); ffma2(a13, wb1, (ull)hb3.y);
        }
        {
            float x, y, v0, v1;
            upk(a00, x, y); v0 = x + y; upk(a10, x, y); v1 = x + y;
            *(float2*)&pscr[0][ks][2 * rp] = make_float2(v0, v1);
            upk(a01, x, y); v0 = x + y; upk(a11, x, y); v1 = x + y;
            *(float2*)&pscr[1][ks][2 * rp] = make_float2(v0, v1);
            upk(a02, x, y); v0 = x + y; upk(a12, x, y); v1 = x + y;
            *(float2*)&pscr[2][ks][2 * rp] = make_float2(v0, v1);
            upk(a03, x, y); v0 = x + y; upk(a13, x, y); v1 = x + y;
            *(float2*)&pscr[3][ks][2 * rp] = make_float2(v0, v1);
        }
        __syncthreads();

        // ---- phase 2: reduce, gate update, DSMEM broadcast
        if (t < 128) {
            float gi = xc0, gf = xc1, gg = xc2, go = xc3;
#pragma unroll
            for (int s = 0; s < 8; s++) {
                gi += pscr[b2][s][u2];
                gf += pscr[b2][s][32 + u2];
                gg += pscr[b2][s][64 + u2];
                go += pscr[b2][s][96 + u2];
            }
            float iv = sigm(gi), fv = sigm(gf), ov = sigm(go);
            float gv = tanh_fast(gg);
            c_reg = fv * c_reg + iv * gv;
            float h = ov * tanh_fast(c_reg);
            hout[((ull)(b0 + b2) * T_ + ts) * H_ + jown] = h;
            uint32_t delta = (uint32_t)((p ^ 1) * NB * H_ * 4);
#pragma unroll
            for (int r = 0; r < CLUSTER; r++)
                asm volatile("st.shared::cluster.f32 [%0], %1;"
                             :: "r"(raj[r] + delta), "f"(h));
        }
        asm volatile("barrier.cluster.arrive.aligned;" ::: "memory");
        // overlap barrier latency with next step's xg prefetch
        if (t < 128) {
            int tn = (ts + 1 < T_) ? (ts + 1) : (T_ - 1);
            const float* xp = xbase + (ull)tn * G4;
            xc0 = xp[0]; xc1 = xp[256]; xc2 = xp[512]; xc3 = xp[768];
        }
        asm volatile("barrier.cluster.wait.aligned;" ::: "memory");
        p ^= 1;
    }
}

// ============================================================================
// FC head — unchanged
// ============================================================================
__global__ __launch_bounds__(128) void fc_head(
    const float* __restrict__ hall, const float* __restrict__ W1,
    const float* __restrict__ b1,   const float* __restrict__ W2,
    const float* __restrict__ b2,   float* __restrict__ out)
{
    __shared__ float hl[H_];
    __shared__ float z[128];
    int b = blockIdx.x, t = threadIdx.x;
    hl[t]       = hall[((ull)b * T_ + (T_ - 1)) * H_ + t];
    hl[t + 128] = hall[((ull)b * T_ + (T_ - 1)) * H_ + t + 128];
    __syncthreads();
    float acc = b1[t];
    const float* w = W1 + t * H_;
#pragma unroll 8
    for (int k = 0; k < H_; k++) acc += w[k] * hl[k];
    z[t] = fmaxf(acc, 0.f);
    __syncthreads();
    if (t < NC_) {
        float a2 = b2[t];
        const float* w2 = W2 + t * 128;
#pragma unroll 8
        for (int k = 0; k < 128; k++) a2 += w2[k] * z[k];
        out[b * NC_ + t] = a2;
    }
}

// ============================================================================
extern "C" void kernel_launch(void* const* d_in, const int* in_sizes, int n_in,
                              void* d_out, int out_size)
{
    const float* x    = (const float*)d_in[0];
    const float* Wih0 = (const float*)d_in[1];
    const float* Whh0 = (const float*)d_in[2];
    const float* b0   = (const float*)d_in[3];
    const float* Wih1 = (const float*)d_in[4];
    const float* Whh1 = (const float*)d_in[5];
    const float* b1   = (const float*)d_in[6];
    const float* Wih2 = (const float*)d_in[7];
    const float* Whh2 = (const float*)d_in[8];
    const float* b2   = (const float*)d_in[9];
    const float* W1   = (const float*)d_in[10];
    const float* bfc1 = (const float*)d_in[11];
    const float* W2   = (const float*)d_in[12];
    const float* bfc2 = (const float*)d_in[13];
    float* out = (float*)d_out;

    float *xg, *h1, *h2;
    cudaGetSymbolAddress((void**)&xg, g_xg);
    cudaGetSymbolAddress((void**)&h1, g_h1);
    cudaGetSymbolAddress((void**)&h2, g_h2);

    dim3 blk(256);
    dim3 grd(G4 / BN, (B_ * T_) / BM);   // (8, 256)
    int rgrid = NCL * CLUSTER;           // 128 CTAs

    // layer 0
    gemm_bias<<<grd, blk>>>(x, Wih0, b0, xg, B_ * T_, G4, IN_);
    lstm_recur_cl<<<rgrid, THR>>>(xg, Whh0, h1);
    // layer 1
    gemm_bias<<<grd, blk>>>(h1, Wih1, b1, xg, B_ * T_, G4, H_);
    lstm_recur_cl<<<rgrid, THR>>>(xg, Whh1, h2);
    // layer 2
    gemm_bias<<<grd, blk>>>(h2, Wih2, b2, xg, B_ * T_, G4, H_);
    lstm_recur_cl<<<rgrid, THR>>>(xg, Whh2, h1);
    // head
    fc_head<<<B_, 128>>>(h1, W1, bfc1, W2, bfc2, out);
}

// round 5
// speedup vs baseline: 7.1302x; 1.0003x over previous
#include <cuda_runtime.h>
#include <cstdint>

// Problem constants
#define B_   64
#define T_   512
#define IN_  1024
#define H_   256
#define G4   1024   // 4*H
#define NC_  8

// Recurrence config
#define CLUSTER   8            // CTAs per cluster
#define NB        4            // batches per cluster
#define NCL       (B_ / NB)    // 16 clusters -> 128 CTAs
#define THR       512          // threads per recurrence CTA

// Scratch (device globals — no allocation allowed)
__device__ float g_xg[B_ * T_ * G4];   // 128 MB: precomputed input gates (B*T, 4H)
__device__ float g_h1[B_ * T_ * H_];
__device__ float g_h2[B_ * T_ * H_];

typedef unsigned long long ull;

// ---- packed f32x2 helpers ----
__device__ __forceinline__ ull pk(float x, float y) {
    ull r; asm("mov.b64 %0, {%1,%2};" : "=l"(r) : "f"(x), "f"(y)); return r;
}
__device__ __forceinline__ void upk(ull v, float &x, float &y) {
    asm("mov.b64 {%0,%1}, %2;" : "=f"(x), "=f"(y) : "l"(v));
}
__device__ __forceinline__ void ffma2(ull &d, ull a, ull b) {
    asm("fma.rn.f32x2 %0, %1, %2, %0;" : "+l"(d) : "l"(a), "l"(b));
}
__device__ __forceinline__ uint32_t smem_u32(const void* p) {
    uint32_t a;
    asm("{ .reg .u64 t; cvta.to.shared.u64 t, %1; cvt.u32.u64 %0, t; }" : "=r"(a) : "l"(p));
    return a;
}
__device__ __forceinline__ float sigm(float x) { return 1.f / (1.f + __expf(-x)); }
__device__ __forceinline__ float tanh_fast(float x) {
    return 1.f - 2.f / (__expf(2.f * x) + 1.f);
}

// ============================================================================
// GEMM: C[M,N] = A[M,K] @ W[N,K]^T + bias[N]   (row-major fp32) — unchanged
// ============================================================================
#define BM 128
#define BN 128
#define BK 16

__global__ __launch_bounds__(256) void gemm_bias(
    const float* __restrict__ A, const float* __restrict__ W,
    const float* __restrict__ bias, float* __restrict__ C,
    int M, int N, int K)
{
    __shared__ float As[BK][BM];
    __shared__ float Bs[BK][BN];
    int t  = threadIdx.x;
    int m0 = blockIdx.y * BM, n0 = blockIdx.x * BN;
    int tx = t & 15, ty = t >> 4;

    ull acc[8][4];
#pragma unroll
    for (int i = 0; i < 8; i++)
#pragma unroll
        for (int j = 0; j < 4; j++) acc[i][j] = 0ull;

    int lr = t >> 2;
    int lc = (t & 3) * 4;

    const float* Ap = A + (ull)(m0 + lr) * K + lc;
    const float* Wp = W + (ull)(n0 + lr) * K + lc;

    for (int k0 = 0; k0 < K; k0 += BK) {
#pragma unroll
        for (int it = 0; it < 2; it++) {
            float4 va = *(const float4*)(Ap + (ull)(it * 64) * K + k0);
            float4 vw = *(const float4*)(Wp + (ull)(it * 64) * K + k0);
            int row = lr + it * 64;
            As[lc + 0][row] = va.x; As[lc + 1][row] = va.y;
            As[lc + 2][row] = va.z; As[lc + 3][row] = va.w;
            Bs[lc + 0][row] = vw.x; Bs[lc + 1][row] = vw.y;
            Bs[lc + 2][row] = vw.z; Bs[lc + 3][row] = vw.w;
        }
        __syncthreads();
#pragma unroll
        for (int k = 0; k < BK; k++) {
            float4 a0 = *(const float4*)&As[k][ty * 8];
            float4 a1 = *(const float4*)&As[k][ty * 8 + 4];
            float4 b0 = *(const float4*)&Bs[k][tx * 8];
            float4 b1 = *(const float4*)&Bs[k][tx * 8 + 4];
            ull bb[4] = { pk(b0.x, b0.y), pk(b0.z, b0.w),
                          pk(b1.x, b1.y), pk(b1.z, b1.w) };
            float av[8] = { a0.x, a0.y, a0.z, a0.w, a1.x, a1.y, a1.z, a1.w };
#pragma unroll
            for (int i = 0; i < 8; i++) {
                ull aa = pk(av[i], av[i]);
#pragma unroll
                for (int j = 0; j < 4; j++) ffma2(acc[i][j], aa, bb[j]);
            }
        }
        __syncthreads();
    }

#pragma unroll
    for (int i = 0; i < 8; i++) {
        int m = m0 + ty * 8 + i;
        float o[8];
#pragma unroll
        for (int j = 0; j < 4; j++) upk(acc[i][j], o[2 * j], o[2 * j + 1]);
#pragma unroll
        for (int j = 0; j < 8; j++) o[j] += bias[n0 + tx * 8 + j];
        *(float4*)&C[(ull)m * N + n0 + tx * 8]     = make_float4(o[0], o[1], o[2], o[3]);
        *(float4*)&C[(ull)m * N + n0 + tx * 8 + 4] = make_float4(o[4], o[5], o[6], o[7]);
    }
}

// ============================================================================
// Cluster LSTM recurrence, weights in REGISTERS.
// 16 clusters x 8 CTAs x 512 thr. Cluster owns 4 batches; CTA rank owns 32
// hidden units (gate rows {g*256+32*rank+u}).
// Thread (rp = t&63, ks = t>>6): gate rows ri=2rp,2rp+1, k-seg [32ks,32ks+32).
// Weights: 32 reg-pairs per thread, loaded once from GMEM.
// Inner loop pairs over k: acc(row,b) += (w_k,w_k+1)*(h_k,h_k+1) — no MOVs.
// h stored batch-major in SMEM so (h_k,h_k+1) is a natural LDS.128 half.
// Per step: phase1 partials -> SMEM; sync; phase2 (128 thr) reduce + gates,
// broadcast h via DSMEM; cluster arrive; prefetch next xg; cluster wait.
// ============================================================================
__global__ __launch_bounds__(THR, 1) __cluster_dims__(CLUSTER, 1, 1)
void lstm_recur_cl(const float* __restrict__ xg, const float* __restrict__ Whh,
                   float* __restrict__ hout)
{
    __shared__ float hsp[2][NB][H_];       // 8 KB, [parity][batch][k]
    __shared__ float pscr[NB][8][128];     // 16 KB, [batch][kseg][ri]

    int t = threadIdx.x;
    uint32_t rank;
    asm("mov.u32 %0, %%cluster_ctarank;" : "=r"(rank));
    int b0 = (blockIdx.x / CLUSTER) * NB;

    int rp = t & 63;          // row pair: ri0=2rp, ri1=2rp+1
    int ks = t >> 6;          // k-segment of 32

    // ---- load weight slice into registers (one time) ----
    // ri -> global row: 256*(ri>>5) + 32*rank + (ri&31); ri0=2rp even so both
    // rows of the pair share the same gate group.
    ull w0[16], w1[16];
    {
        int g = rp >> 4;
        int u = (2 * rp) & 31;
        const float* p0 = Whh + (ull)(256 * g + 32 * (int)rank + u) * H_ + 32 * ks;
        const float* p1 = p0 + H_;
#pragma unroll
        for (int j = 0; j < 16; j++) {
            w0[j] = *(const ull*)(p0 + 2 * j);
            w1[j] = *(const ull*)(p1 + 2 * j);
        }
    }
    // zero h buffers
    for (int i = t; i < 2 * NB * H_; i += THR) ((float*)hsp)[i] = 0.f;
    __syncthreads();
    asm volatile("barrier.cluster.arrive.aligned;" ::: "memory");
    asm volatile("barrier.cluster.wait.aligned;" ::: "memory");

    // phase-2 identity (threads 0..127): unit u2, batch b2
    int u2 = t & 31, b2 = (t >> 5) & 3;
    float c_reg = 0.f;
    int jown = 32 * (int)rank + u2;

    // hoisted mapa: remote addr of hsp[0][b2][jown] in each peer CTA
    uint32_t raj[CLUSTER];
    {
        uint32_t loc = smem_u32(&hsp[0][b2][jown]);
#pragma unroll
        for (int r = 0; r < CLUSTER; r++)
            asm("mapa.shared::cluster.u32 %0, %1, %2;" : "=r"(raj[r]) : "r"(loc), "r"(r));
    }

    const float* xbase = xg + (ull)(b0 + b2) * T_ * G4 + jown;
    // prefetch xg for ts=0
    float xc0, xc1, xc2, xc3;
    if (t < 128) {
        xc0 = xbase[0]; xc1 = xbase[256]; xc2 = xbase[512]; xc3 = xbase[768];
    }

    int p = 0;
    for (int ts = 0; ts < T_; ts++) {
        // ---- phase 1: partial dots over this thread's 32-k segment
        ull a00 = 0, a01 = 0, a02 = 0, a03 = 0;   // row0 x batch
        ull a10 = 0, a11 = 0, a12 = 0, a13 = 0;   // row1 x batch
        const float* hseg = &hsp[p][0][32 * ks];
#pragma unroll
        for (int j2 = 0; j2 < 8; j2++) {
            longlong2 hb0 = *(const longlong2*)(hseg + 0 * H_ + 4 * j2);
            longlong2 hb1 = *(const longlong2*)(hseg + 1 * H_ + 4 * j2);
            longlong2 hb2 = *(const longlong2*)(hseg + 2 * H_ + 4 * j2);
            longlong2 hb3 = *(const longlong2*)(hseg + 3 * H_ + 4 * j2);
            ull wa0 = w0[2 * j2], wb0 = w0[2 * j2 + 1];
            ull wa1 = w1[2 * j2], wb1 = w1[2 * j2 + 1];
            ffma2(a00, wa0, (ull)hb0.x); ffma2(a00, wb0, (ull)hb0.y);
            ffma2(a01, wa0, (ull)hb1.x); ffma2(a01, wb0, (ull)hb1.y);
            ffma2(a02, wa0, (ull)hb2.x); ffma2(a02, wb0, (ull)hb2.y);
            ffma2(a03, wa0, (ull)hb3.x); ffma2(a03, wb0, (ull)hb3.y);
            ffma2(a10, wa1, (ull)hb0.x); ffma2(a10, wb1, (ull)hb0.y);
            ffma2(a11, wa1, (ull)hb1.x); ffma2(a11, wb1, (ull)hb1.y);
            ffma2(a12, wa1, (ull)hb2.x); ffma2(a12, wb1, (ull)hb2.y);
            ffma2(a13, wa1, (ull)hb3.x); ffma2(a13, wb1, (ull)hb3.y);
        }
        {
            float x, y, v0, v1;
            upk(a00, x, y); v0 = x + y; upk(a10, x, y); v1 = x + y;
            *(float2*)&pscr[0][ks][2 * rp] = make_float2(v0, v1);
            upk(a01, x, y); v0 = x + y; upk(a11, x, y); v1 = x + y;
            *(float2*)&pscr[1][ks][2 * rp] = make_float2(v0, v1);
            upk(a02, x, y); v0 = x + y; upk(a12, x, y); v1 = x + y;
            *(float2*)&pscr[2][ks][2 * rp] = make_float2(v0, v1);
            upk(a03, x, y); v0 = x + y; upk(a13, x, y); v1 = x + y;
            *(float2*)&pscr[3][ks][2 * rp] = make_float2(v0, v1);
        }
        __syncthreads();

        // ---- phase 2: reduce, gate update, DSMEM broadcast
        if (t < 128) {
            float gi = xc0, gf = xc1, gg = xc2, go = xc3;
#pragma unroll
            for (int s = 0; s < 8; s++) {
                gi += pscr[b2][s][u2];
                gf += pscr[b2][s][32 + u2];
                gg += pscr[b2][s][64 + u2];
                go += pscr[b2][s][96 + u2];
            }
            float iv = sigm(gi), fv = sigm(gf), ov = sigm(go);
            float gv = tanh_fast(gg);
            c_reg = fv * c_reg + iv * gv;
            float h = ov * tanh_fast(c_reg);
            hout[((ull)(b0 + b2) * T_ + ts) * H_ + jown] = h;
            uint32_t delta = (uint32_t)((p ^ 1) * NB * H_ * 4);
#pragma unroll
            for (int r = 0; r < CLUSTER; r++)
                asm volatile("st.shared::cluster.f32 [%0], %1;"
                             :: "r"(raj[r] + delta), "f"(h));
        }
        asm volatile("barrier.cluster.arrive.aligned;" ::: "memory");
        // overlap barrier latency with next step's xg prefetch
        if (t < 128) {
            int tn = (ts + 1 < T_) ? (ts + 1) : (T_ - 1);
            const float* xp = xbase + (ull)tn * G4;
            xc0 = xp[0]; xc1 = xp[256]; xc2 = xp[512]; xc3 = xp[768];
        }
        asm volatile("barrier.cluster.wait.aligned;" ::: "memory");
        p ^= 1;
    }
}

// ============================================================================
// FC head — unchanged
// ============================================================================
__global__ __launch_bounds__(128) void fc_head(
    const float* __restrict__ hall, const float* __restrict__ W1,
    const float* __restrict__ b1,   const float* __restrict__ W2,
    const float* __restrict__ b2,   float* __restrict__ out)
{
    __shared__ float hl[H_];
    __shared__ float z[128];
    int b = blockIdx.x, t = threadIdx.x;
    hl[t]       = hall[((ull)b * T_ + (T_ - 1)) * H_ + t];
    hl[t + 128] = hall[((ull)b * T_ + (T_ - 1)) * H_ + t + 128];
    __syncthreads();
    float acc = b1[t];
    const float* w = W1 + t * H_;
#pragma unroll 8
    for (int k = 0; k < H_; k++) acc += w[k] * hl[k];
    z[t] = fmaxf(acc, 0.f);
    __syncthreads();
    if (t < NC_) {
        float a2 = b2[t];
        const float* w2 = W2 + t * 128;
#pragma unroll 8
        for (int k = 0; k < 128; k++) a2 += w2[k] * z[k];
        out[b * NC_ + t] = a2;
    }
}

// ============================================================================
extern "C" void kernel_launch(void* const* d_in, const int* in_sizes, int n_in,
                              void* d_out, int out_size)
{
    const float* x    = (const float*)d_in[0];
    const float* Wih0 = (const float*)d_in[1];
    const float* Whh0 = (const float*)d_in[2];
    const float* b0   = (const float*)d_in[3];
    const float* Wih1 = (const float*)d_in[4];
    const float* Whh1 = (const float*)d_in[5];
    const float* b1   = (const float*)d_in[6];
    const float* Wih2 = (const float*)d_in[7];
    const float* Whh2 = (const float*)d_in[8];
    const float* b2   = (const float*)d_in[9];
    const float* W1   = (const float*)d_in[10];
    const float* bfc1 = (const float*)d_in[11];
    const float* W2   = (const float*)d_in[12];
    const float* bfc2 = (const float*)d_in[13];
    float* out = (float*)d_out;

    float *xg, *h1, *h2;
    cudaGetSymbolAddress((void**)&xg, g_xg);
    cudaGetSymbolAddress((void**)&h1, g_h1);
    cudaGetSymbolAddress((void**)&h2, g_h2);

    dim3 blk(256);
    dim3 grd(G4 / BN, (B_ * T_) / BM);   // (8, 256)
    int rgrid = NCL * CLUSTER;           // 128 CTAs

    // layer 0
    gemm_bias<<<grd, blk>>>(x, Wih0, b0, xg, B_ * T_, G4, IN_);
    lstm_recur_cl<<<rgrid, THR>>>(xg, Whh0, h1);
    // layer 1
    gemm_bias<<<grd, blk>>>(h1, Wih1, b1, xg, B_ * T_, G4, H_);
    lstm_recur_cl<<<rgrid, THR>>>(xg, Whh1, h2);
    // layer 2
    gemm_bias<<<grd, blk>>>(h2, Wih2, b2, xg, B_ * T_, G4, H_);
    lstm_recur_cl<<<rgrid, THR>>>(xg, Whh2, h1);
    // head
    fc_head<<<B_, 128>>>(h1, W1, bfc1, W2, bfc2, out);
}

// round 7
// speedup vs baseline: 8.4175x; 1.1805x over previous
#include <cuda_runtime.h>
#include <cuda_bf16.h>
#include <cstdint>

#define B_   64
#define T_   512
#define IN_  1024
#define H_   256
#define G4   1024
#define NC_  8

typedef unsigned long long ull;

__device__ float g_xg[B_ * T_ * G4];
__device__ float g_h1[B_ * T_ * H_];
__device__ float g_h2[B_ * T_ * H_];

__device__ __forceinline__ ull pk(float x, float y) {
    ull r; asm("mov.b64 %0, {%1,%2};" : "=l"(r) : "f"(x), "f"(y)); return r;
}
__device__ __forceinline__ void upk(ull v, float &x, float &y) {
    asm("mov.b64 {%0,%1}, %2;" : "=f"(x), "=f"(y) : "l"(v));
}
__device__ __forceinline__ void ffma2(ull &d, ull a, ull b) {
    asm("fma.rn.f32x2 %0, %1, %2, %0;" : "+l"(d) : "l"(a), "l"(b));
}
__device__ __forceinline__ uint32_t smem_u32(const void* p) {
    uint32_t a;
    asm("{ .reg .u64 t; cvta.to.shared.u64 t, %1; cvt.u32.u64 %0, t; }" : "=r"(a) : "l"(p));
    return a;
}

// ---- MUFU-free exp / reciprocal (FMA+ALU pipes only) ----
__device__ __forceinline__ float fexp(float x) {   // e^x, |x| <= ~24
    float z = x * 1.4426950408889634f;
    float t = z + 12582912.0f;                     // round-to-nearest int
    int n = __float_as_int(t) - 0x4B400000;
    float f = z - (t - 12582912.0f);               // f in [-0.5, 0.5]
    float p = 1.5403530394e-4f;
    p = fmaf(p, f, 1.3333558147e-3f);
    p = fmaf(p, f, 9.6181291891e-3f);
    p = fmaf(p, f, 5.5504108665e-2f);
    p = fmaf(p, f, 2.4022650696e-1f);
    p = fmaf(p, f, 6.9314718056e-1f);
    p = fmaf(p, f, 1.0f);
    return __int_as_float(__float_as_int(p) + (n << 23));
}
__device__ __forceinline__ float frcp(float d) {   // 1/d, d in [1, ~1e7]
    float r = __int_as_float(0x7EF311C3 - __float_as_int(d));
    r = r * fmaf(-d, r, 2.0f);
    r = r * fmaf(-d, r, 2.0f);
    r = r * fmaf(-d, r, 2.0f);
    return r;
}
__device__ __forceinline__ float sigm_f(float x) {
    float xx = fminf(fmaxf(x, -15.f), 15.f);
    return frcp(1.0f + fexp(-xx));
}
__device__ __forceinline__ float tanh_f(float x) {
    float xx = fminf(fmaxf(x, -8.f), 8.f);
    return fmaf(-2.0f, frcp(fexp(2.0f * xx) + 1.0f), 1.0f);
}

// ============================================================================
// fp32 GEMM with f32x2 FMAs (unchanged — known 2.35 ms)
// ============================================================================
#define BM 128
#define BN 128
#define BK 16

__global__ __launch_bounds__(256) void gemm_bias(
    const float* __restrict__ A, const float* __restrict__ W,
    const float* __restrict__ bias, float* __restrict__ C,
    int M, int N, int K)
{
    __shared__ float As[BK][BM];
    __shared__ float Bs[BK][BN];
    int t  = threadIdx.x;
    int m0 = blockIdx.y * BM, n0 = blockIdx.x * BN;
    int tx = t & 15, ty = t >> 4;

    ull acc[8][4];
#pragma unroll
    for (int i = 0; i < 8; i++)
#pragma unroll
        for (int j = 0; j < 4; j++) acc[i][j] = 0ull;

    int lr = t >> 2;
    int lc = (t & 3) * 4;
    const float* Ap = A + (ull)(m0 + lr) * K + lc;
    const float* Wp = W + (ull)(n0 + lr) * K + lc;

    for (int k0 = 0; k0 < K; k0 += BK) {
#pragma unroll
        for (int it = 0; it < 2; it++) {
            float4 va = *(const float4*)(Ap + (ull)(it * 64) * K + k0);
            float4 vw = *(const float4*)(Wp + (ull)(it * 64) * K + k0);
            int row = lr + it * 64;
            As[lc + 0][row] = va.x; As[lc + 1][row] = va.y;
            As[lc + 2][row] = va.z; As[lc + 3][row] = va.w;
            Bs[lc + 0][row] = vw.x; Bs[lc + 1][row] = vw.y;
            Bs[lc + 2][row] = vw.z; Bs[lc + 3][row] = vw.w;
        }
        __syncthreads();
#pragma unroll
        for (int k = 0; k < BK; k++) {
            float4 a0 = *(const float4*)&As[k][ty * 8];
            float4 a1 = *(const float4*)&As[k][ty * 8 + 4];
            float4 b0 = *(const float4*)&Bs[k][tx * 8];
            float4 b1 = *(const float4*)&Bs[k][tx * 8 + 4];
            ull bb[4] = { pk(b0.x, b0.y), pk(b0.z, b0.w),
                          pk(b1.x, b1.y), pk(b1.z, b1.w) };
            float av[8] = { a0.x, a0.y, a0.z, a0.w, a1.x, a1.y, a1.z, a1.w };
#pragma unroll
            for (int i = 0; i < 8; i++) {
                ull aa = pk(av[i], av[i]);
#pragma unroll
                for (int j = 0; j < 4; j++) ffma2(acc[i][j], aa, bb[j]);
            }
        }
        __syncthreads();
    }

#pragma unroll
    for (int i = 0; i < 8; i++) {
        int m = m0 + ty * 8 + i;
        float o[8];
#pragma unroll
        for (int j = 0; j < 4; j++) upk(acc[i][j], o[2 * j], o[2 * j + 1]);
#pragma unroll
        for (int j = 0; j < 8; j++) o[j] += bias[n0 + tx * 8 + j];
        *(float4*)&C[(ull)m * N + n0 + tx * 8]     = make_float4(o[0], o[1], o[2], o[3]);
        *(float4*)&C[(ull)m * N + n0 + tx * 8 + 4] = make_float4(o[4], o[5], o[6], o[7]);
    }
}

// ============================================================================
// LSTM recurrence via mma.sync.m16n8k16 bf16 (split hi/lo, 3 products).
// 8 clusters x 8 CTAs x 256 thr. CTA rank owns units [32r,32r+32) ->
// 128 gate rows ri=4u+g (global row 256g+32r+u). N=8 batches. K=256=16 kt.
// A fragments (hi+lo) in registers (loaded once). h exchanged as packed
// (bf16hi | bf16lo<<16) u32 via DSMEM + mbarrier, double-buffered by parity.
// ============================================================================
#define RT_CL 8

__device__ __forceinline__ void mma16816(float* d, const uint32_t* a,
                                         uint32_t b0, uint32_t b1) {
    asm volatile(
        "mma.sync.aligned.m16n8k16.row.col.f32.bf16.bf16.f32 "
        "{%0,%1,%2,%3}, {%4,%5,%6,%7}, {%8,%9}, {%0,%1,%2,%3};"
        : "+f"(d[0]), "+f"(d[1]), "+f"(d[2]), "+f"(d[3])
        : "r"(a[0]), "r"(a[1]), "r"(a[2]), "r"(a[3]), "r"(b0), "r"(b1));
}
__device__ __forceinline__ void sp2(float2 f, uint32_t& hi, uint32_t& lo) {
    __nv_bfloat162 h = __float22bfloat162_rn(f);
    float2 hf = __bfloat1622float2(h);
    __nv_bfloat162 l = __float22bfloat162_rn(make_float2(f.x - hf.x, f.y - hf.y));
    hi = *(uint32_t*)&h; lo = *(uint32_t*)&l;
}
__device__ __forceinline__ void mbar_wait_acqc(uint32_t a, int ph) {
    asm volatile("{\n\t.reg .pred P;\n\tW%=:\n\t"
                 "mbarrier.try_wait.parity.acquire.cluster.shared::cta.b64 P, [%0], %1;\n\t"
                 "@!P bra W%=;\n\t}" :: "r"(a), "r"(ph) : "memory");
}

__global__ __launch_bounds__(256, 1) __cluster_dims__(RT_CL, 1, 1)
void lstm_recur_mma(const float* __restrict__ xg, const float* __restrict__ Whh,
                    float* __restrict__ hout)
{
    __shared__ unsigned short Bfh16[16 * 32 * 4];   // B frag hi  (ull view [kt][lane])
    __shared__ unsigned short Bfl16[16 * 32 * 4];   // B frag lo
    __shared__ uint32_t hbuf[2][256 * 8];           // packed (hhi|hlo<<16), [k][b]
    __shared__ float PRE[8 * 132];                  // [b][ri], pitch 132
    __shared__ uint32_t stg[32 * 9];                // [u][b], pitch 9
    __shared__ __align__(8) ull bars[2];

    int t = threadIdx.x;
    int w = t >> 5, lane = t & 31;
    uint32_t rank;
    asm("mov.u32 %0, %%cluster_ctarank;" : "=r"(rank));
    int b0 = (blockIdx.x / RT_CL) * 8;

    uint32_t barsb = smem_u32(bars);
    if (t == 0) {
        asm volatile("mbarrier.init.shared.b64 [%0], %1;" :: "r"(barsb),     "r"(128) : "memory");
        asm volatile("mbarrier.init.shared.b64 [%0], %1;" :: "r"(barsb + 8), "r"(128) : "memory");
    }

    // ---- one-time: A fragments (hi/lo) into registers ----
    int r0 = 16 * w + (lane >> 2);          // D/A row (r0 and r0+8)
    int k0 = (lane & 3) * 2;                // D col / A k base
    uint32_t ahi[16][4], alo[16][4];
    {
        int g0 = r0 & 3, u0 = r0 >> 2;
        const float* W0 = Whh + (ull)(256 * g0 + 32 * (int)rank + u0) * H_;
        const float* W1 = W0 + 2 * H_;      // row r0+8: same gate, unit+2
#pragma unroll
        for (int kt = 0; kt < 16; kt++) {
            float2 f0 = *(const float2*)(W0 + k0 + 16 * kt);
            float2 f1 = *(const float2*)(W1 + k0 + 16 * kt);
            float2 f2 = *(const float2*)(W0 + k0 + 16 * kt + 8);
            float2 f3 = *(const float2*)(W1 + k0 + 16 * kt + 8);
            sp2(f0, ahi[kt][0], alo[kt][0]);
            sp2(f1, ahi[kt][1], alo[kt][1]);
            sp2(f2, ahi[kt][2], alo[kt][2]);
            sp2(f3, ahi[kt][3], alo[kt][3]);
        }
    }
    for (int i = t; i < 2 * 2048; i += 256) ((uint32_t*)hbuf)[i] = 0;
    __syncthreads();
    asm volatile("barrier.cluster.arrive.aligned;" ::: "memory");
    asm volatile("barrier.cluster.wait.aligned;" ::: "memory");

    // conversion constants (thread t handles global k = t)
    int ckt = t >> 4, ckk = t & 15;
    int cq = (ckk & 7) >> 1;
    int cp = (ckk & 1) + ((ckk >> 3) << 1);

    // pusher constants (t<128): target CTA tgt, units 2*(t&15), +1
    int tgt = t >> 4;
    uint32_t rH, rBar;
    asm("mapa.shared::cluster.u32 %0, %1, %2;" : "=r"(rH)   : "r"(smem_u32(hbuf)), "r"(tgt));
    asm("mapa.shared::cluster.u32 %0, %1, %2;" : "=r"(rBar) : "r"(barsb),          "r"(tgt));

    // gate constants: thread = (u=lane, bb=w)
    float c_reg = 0.f;
    int jown = 32 * (int)rank + lane;

    // xg pointers for this thread's 4 D cells
    int grow0 = 256 * (r0 & 3) + 32 * (int)rank + (r0 >> 2);
    const float* xp0 = xg + (ull)(b0 + k0) * T_ * G4 + grow0;
    const float* xp1 = xg + (ull)(b0 + k0 + 1) * T_ * G4 + grow0;

    int ph0 = 0, ph1 = 0;
    ull* Bfh64 = (ull*)Bfh16;
    ull* Bfl64 = (ull*)Bfl16;

    for (int ts = 0; ts < T_; ts++) {
        int p = ts & 1;
        if (ts) {
            if (p) { mbar_wait_acqc(barsb + 8, ph1); ph1 ^= 1; }
            else   { mbar_wait_acqc(barsb,     ph0); ph0 ^= 1; }
        }
        // prefetch xg (consumed after mma)
        float x00 = xp0[0], x02 = xp0[2], x01 = xp1[0], x03 = xp1[2];
        xp0 += G4; xp1 += G4;

        // ---- build B fragments from hbuf[p]
        {
            const uint32_t* hb = &hbuf[p][t * 8];
            uint4 va = *(const uint4*)hb;
            uint4 vb = *(const uint4*)(hb + 4);
            uint32_t vv[8] = { va.x, va.y, va.z, va.w, vb.x, vb.y, vb.z, vb.w };
#pragma unroll
            for (int b = 0; b < 8; b++) {
                int idx = (ckt * 32 + 4 * b + cq) * 4 + cp;
                Bfh16[idx] = (unsigned short)(vv[b] & 0xFFFF);
                Bfl16[idx] = (unsigned short)(vv[b] >> 16);
            }
        }
        __syncthreads();

        // ---- 48 mma (3 products x 16 kt), 3 accumulators
        float aA[4] = {0, 0, 0, 0}, aB[4] = {0, 0, 0, 0}, aC[4] = {0, 0, 0, 0};
#pragma unroll
        for (int kt = 0; kt < 16; kt++) {
            ull bh = Bfh64[kt * 32 + lane];
            ull bl = Bfl64[kt * 32 + lane];
            uint32_t bh0 = (uint32_t)bh, bh1 = (uint32_t)(bh >> 32);
            uint32_t bl0 = (uint32_t)bl, bl1 = (uint32_t)(bl >> 32);
            mma16816(aA, ahi[kt], bh0, bh1);
            mma16816(aB, ahi[kt], bl0, bl1);
            mma16816(aC, alo[kt], bh0, bh1);
        }
        // preact = D + xg -> PRE[b][ri]
        PRE[(k0)     * 132 + r0]     = aA[0] + aB[0] + aC[0] + x00;
        PRE[(k0 + 1) * 132 + r0]     = aA[1] + aB[1] + aC[1] + x01;
        PRE[(k0)     * 132 + r0 + 8] = aA[2] + aB[2] + aC[2] + x02;
        PRE[(k0 + 1) * 132 + r0 + 8] = aA[3] + aB[3] + aC[3] + x03;
        __syncthreads();

        // ---- gates: thread (u=lane, bb=w), MUFU-free
        {
            float4 v = *(const float4*)&PRE[w * 132 + 4 * lane];
            float iv = sigm_f(v.x), fv = sigm_f(v.y), ov = sigm_f(v.w);
            float gv = tanh_f(v.z);
            c_reg = fv * c_reg + iv * gv;
            float h = ov * tanh_f(c_reg);
            hout[((ull)(b0 + w) * T_ + ts) * H_ + jown] = h;
            __nv_bfloat16 hh = __float2bfloat16(h);
            __nv_bfloat16 hl = __float2bfloat16(h - __bfloat162float(hh));
            stg[lane * 9 + w] = (uint32_t)__bfloat16_as_ushort(hh)
                              | ((uint32_t)__bfloat16_as_ushort(hl) << 16);
        }
        __syncthreads();

        // ---- push 2 units' packed h to target CTA's hbuf[p^1]
        if (t < 128) {
            uint32_t dbase = rH + (uint32_t)((p ^ 1) * 8192);
            int uA = (t & 15) * 2;
#pragma unroll
            for (int e = 0; e < 2; e++) {
                int u = uA + e;
                const uint32_t* s = &stg[u * 9];
                ull v0 = (ull)s[0] | ((ull)s[1] << 32);
                ull v1 = (ull)s[2] | ((ull)s[3] << 32);
                ull v2 = (ull)s[4] | ((ull)s[5] << 32);
                ull v3 = (ull)s[6] | ((ull)s[7] << 32);
                uint32_t dst = dbase + (uint32_t)((32 * (int)rank + u) * 32);
                asm volatile("st.shared::cluster.u64 [%0], %1;" :: "r"(dst),      "l"(v0) : "memory");
                asm volatile("st.shared::cluster.u64 [%0], %1;" :: "r"(dst + 8),  "l"(v1) : "memory");
                asm volatile("st.shared::cluster.u64 [%0], %1;" :: "r"(dst + 16), "l"(v2) : "memory");
                asm volatile("st.shared::cluster.u64 [%0], %1;" :: "r"(dst + 24), "l"(v3) : "memory");
            }
            asm volatile("mbarrier.arrive.release.cluster.shared::cluster.b64 _, [%0];"
                         :: "r"(rBar + (uint32_t)((p ^ 1) * 8)) : "memory");
        }
    }

    asm volatile("barrier.cluster.arrive.aligned;" ::: "memory");
    asm volatile("barrier.cluster.wait.aligned;" ::: "memory");
}

// ============================================================================
// FC head (unchanged)
// ============================================================================
__global__ __launch_bounds__(128) void fc_head(
    const float* __restrict__ hall, const float* __restrict__ W1,
    const float* __restrict__ b1,   const float* __restrict__ W2,
    const float* __restrict__ b2,   float* __restrict__ out)
{
    __shared__ float hl[H_];
    __shared__ float z[128];
    int b = blockIdx.x, t = threadIdx.x;
    hl[t]       = hall[((ull)b * T_ + (T_ - 1)) * H_ + t];
    hl[t + 128] = hall[((ull)b * T_ + (T_ - 1)) * H_ + t + 128];
    __syncthreads();
    float acc = b1[t];
    const float* ww = W1 + t * H_;
#pragma unroll 8
    for (int k = 0; k < H_; k++) acc += ww[k] * hl[k];
    z[t] = fmaxf(acc, 0.f);
    __syncthreads();
    if (t < NC_) {
        float a2 = b2[t];
        const float* w2 = W2 + t * 128;
#pragma unroll 8
        for (int k = 0; k < 128; k++) a2 += w2[k] * z[k];
        out[b * NC_ + t] = a2;
    }
}

// ============================================================================
extern "C" void kernel_launch(void* const* d_in, const int* in_sizes, int n_in,
                              void* d_out, int out_size)
{
    const float* x    = (const float*)d_in[0];
    const float* Wih0 = (const float*)d_in[1];
    const float* Whh0 = (const float*)d_in[2];
    const float* b0   = (const float*)d_in[3];
    const float* Wih1 = (const float*)d_in[4];
    const float* Whh1 = (const float*)d_in[5];
    const float* b1   = (const float*)d_in[6];
    const float* Wih2 = (const float*)d_in[7];
    const float* Whh2 = (const float*)d_in[8];
    const float* b2   = (const float*)d_in[9];
    const float* W1   = (const float*)d_in[10];
    const float* bfc1 = (const float*)d_in[11];
    const float* W2   = (const float*)d_in[12];
    const float* bfc2 = (const float*)d_in[13];
    float* out = (float*)d_out;

    float *xg, *h1, *h2;
    cudaGetSymbolAddress((void**)&xg, g_xg);
    cudaGetSymbolAddress((void**)&h1, g_h1);
    cudaGetSymbolAddress((void**)&h2, g_h2);

    dim3 blk(256);
    dim3 grd(G4 / BN, (B_ * T_) / BM);
    int rgrid = (B_ / 8) * RT_CL;   // 64 CTAs = 8 clusters

    gemm_bias<<<grd, blk>>>(x, Wih0, b0, xg, B_ * T_, G4, IN_);
    lstm_recur_mma<<<rgrid, 256>>>(xg, Whh0, h1);
    gemm_bias<<<grd, blk>>>(h1, Wih1, b1, xg, B_ * T_, G4, H_);
    lstm_recur_mma<<<rgrid, 256>>>(xg, Whh1, h2);
    gemm_bias<<<grd, blk>>>(h2, Wih2, b2, xg, B_ * T_, G4, H_);
    lstm_recur_mma<<<rgrid, 256>>>(xg, Whh2, h1);
    fc_head<<<B_, 128>>>(h1, W1, bfc1, W2, bfc2, out);
}

// round 8
// speedup vs baseline: 11.2444x; 1.3358x over previous
#include <cuda_runtime.h>
#include <cuda_bf16.h>
#include <cstdint>

#define B_   64
#define T_   512
#define IN_  1024
#define H_   256
#define G4   1024
#define NC_  8

typedef unsigned long long ull;

// ---- scratch (device globals; no allocation allowed) ----
__device__ float    g_xg[B_ * T_ * G4];    // gate preactivations fp32
__device__ uint32_t g_as[B_ * T_ * IN_];   // split-packed x
__device__ uint32_t g_hs1[B_ * T_ * H_];   // split-packed h (layer outs)
__device__ uint32_t g_hs2[B_ * T_ * H_];
__device__ uint32_t g_ws[G4 * IN_];        // split-packed Wih (reused per layer)

__device__ __forceinline__ uint32_t smem_u32(const void* p) {
    uint32_t a;
    asm("{ .reg .u64 t; cvta.to.shared.u64 t, %1; cvt.u32.u64 %0, t; }" : "=r"(a) : "l"(p));
    return a;
}
__device__ __forceinline__ uint32_t prmt(uint32_t a, uint32_t b, uint32_t s) {
    uint32_t r; asm("prmt.b32 %0,%1,%2,%3;" : "=r"(r) : "r"(a), "r"(b), "r"(s)); return r;
}
__device__ __forceinline__ uint32_t ps32(float f) {   // packed split bf16
    __nv_bfloat16 h = __float2bfloat16(f);
    __nv_bfloat16 l = __float2bfloat16(f - __bfloat162float(h));
    return (uint32_t)__bfloat16_as_ushort(h) | ((uint32_t)__bfloat16_as_ushort(l) << 16);
}
__device__ __forceinline__ float ups(uint32_t v) {
    return __bfloat162float(__ushort_as_bfloat16((unsigned short)(v & 0xFFFF)))
         + __bfloat162float(__ushort_as_bfloat16((unsigned short)(v >> 16)));
}

// ---- MUFU-free exp / rcp ----
__device__ __forceinline__ float fexp(float x) {
    float z = x * 1.4426950408889634f;
    float t = z + 12582912.0f;
    int n = __float_as_int(t) - 0x4B400000;
    float f = z - (t - 12582912.0f);
    float p = 1.5403530394e-4f;
    p = fmaf(p, f, 1.3333558147e-3f);
    p = fmaf(p, f, 9.6181291891e-3f);
    p = fmaf(p, f, 5.5504108665e-2f);
    p = fmaf(p, f, 2.4022650696e-1f);
    p = fmaf(p, f, 6.9314718056e-1f);
    p = fmaf(p, f, 1.0f);
    return __int_as_float(__float_as_int(p) + (n << 23));
}
__device__ __forceinline__ float frcp(float d) {
    float r = __int_as_float(0x7EF311C3 - __float_as_int(d));
    r = r * fmaf(-d, r, 2.0f);
    r = r * fmaf(-d, r, 2.0f);
    r = r * fmaf(-d, r, 2.0f);
    return r;
}
__device__ __forceinline__ float sigm_f(float x) {
    float xx = fminf(fmaxf(x, -15.f), 15.f);
    return frcp(1.0f + fexp(-xx));
}
__device__ __forceinline__ float tanh_f(float x) {
    float xx = fminf(fmaxf(x, -8.f), 8.f);
    return fmaf(-2.0f, frcp(fexp(2.0f * xx) + 1.0f), 1.0f);
}

__device__ __forceinline__ void mma16816(float* d, const uint32_t* a,
                                         uint32_t b0, uint32_t b1) {
    asm volatile(
        "mma.sync.aligned.m16n8k16.row.col.f32.bf16.bf16.f32 "
        "{%0,%1,%2,%3}, {%4,%5,%6,%7}, {%8,%9}, {%0,%1,%2,%3};"
        : "+f"(d[0]), "+f"(d[1]), "+f"(d[2]), "+f"(d[3])
        : "r"(a[0]), "r"(a[1]), "r"(a[2]), "r"(a[3]), "r"(b0), "r"(b1));
}
__device__ __forceinline__ void ldsm4(uint32_t* r, uint32_t addr) {
    asm volatile("ldmatrix.sync.aligned.m8n8.x4.shared.b16 {%0,%1,%2,%3}, [%4];"
                 : "=r"(r[0]), "=r"(r[1]), "=r"(r[2]), "=r"(r[3]) : "r"(addr));
}
__device__ __forceinline__ void sp2(float2 f, uint32_t& hi, uint32_t& lo) {
    __nv_bfloat162 h = __float22bfloat162_rn(f);
    float2 hf = __bfloat1622float2(h);
    __nv_bfloat162 l = __float22bfloat162_rn(make_float2(f.x - hf.x, f.y - hf.y));
    hi = *(uint32_t*)&h; lo = *(uint32_t*)&l;
}
__device__ __forceinline__ void mbar_wait_acqc(uint32_t a, int ph) {
    asm volatile("{\n\t.reg .pred P;\n\tW%=:\n\t"
                 "mbarrier.try_wait.parity.acquire.cluster.shared::cta.b64 P, [%0], %1;\n\t"
                 "@!P bra W%=;\n\t}" :: "r"(a), "r"(ph) : "memory");
}

// ============================================================================
// split pre-pass: fp32 -> packed split bf16 (hi | lo<<16)
// ============================================================================
__global__ __launch_bounds__(256) void split_ps(const float* __restrict__ in,
                                                uint32_t* __restrict__ out, int n4) {
    int i = blockIdx.x * 256 + threadIdx.x;
    if (i < n4) {
        float4 v = ((const float4*)in)[i];
        uint4 o;
        o.x = ps32(v.x); o.y = ps32(v.y); o.z = ps32(v.z); o.w = ps32(v.w);
        ((uint4*)out)[i] = o;
    }
}

// ============================================================================
// Tensor GEMM: C[M,1024] = A[M,K](ps32) @ W[1024,K](ps32)^T + bias
// 128x128x16 tiles, 8 warps x (32x64), split-bf16 3-product into one acc.
// ============================================================================
__global__ __launch_bounds__(256) void gemm_tc(
    const uint32_t* __restrict__ A, const uint32_t* __restrict__ W,
    const float* __restrict__ bias, float* __restrict__ C, int K)
{
    // [stage][plane: Ahi,Alo,Whi,Wlo][row*16 + k]  bf16
    __shared__ __align__(16) unsigned short sm[2][4][128 * 16];
    int t = threadIdx.x, lane = t & 31, w = t >> 5;
    int m0 = blockIdx.y * 128, n0 = blockIdx.x * 128;
    int mi = w & 3, nj = w >> 2;
    int K16 = K / 16;

    int row = t >> 1, half = t & 1;
    const uint32_t* gA = A + (ull)(m0 + row) * K + half * 8;
    const uint32_t* gW = W + (ull)(n0 + row) * K + half * 8;

    uint4 ra0, ra1, rw0, rw1;
    auto LDG = [&](int kk) {
        const uint32_t* pa = gA + kk * 16;
        const uint32_t* pw = gW + kk * 16;
        ra0 = *(const uint4*)pa; ra1 = *(const uint4*)(pa + 4);
        rw0 = *(const uint4*)pw; rw1 = *(const uint4*)(pw + 4);
    };
    auto STS = [&](int st) {
        uint32_t p[8] = { ra0.x, ra0.y, ra0.z, ra0.w, ra1.x, ra1.y, ra1.z, ra1.w };
        uint32_t q[8] = { rw0.x, rw0.y, rw0.z, rw0.w, rw1.x, rw1.y, rw1.z, rw1.w };
        uint4 ahi, alo, whi, wlo;
        ahi.x = prmt(p[0], p[1], 0x5410); alo.x = prmt(p[0], p[1], 0x7632);
        ahi.y = prmt(p[2], p[3], 0x5410); alo.y = prmt(p[2], p[3], 0x7632);
        ahi.z = prmt(p[4], p[5], 0x5410); alo.z = prmt(p[4], p[5], 0x7632);
        ahi.w = prmt(p[6], p[7], 0x5410); alo.w = prmt(p[6], p[7], 0x7632);
        whi.x = prmt(q[0], q[1], 0x5410); wlo.x = prmt(q[0], q[1], 0x7632);
        whi.y = prmt(q[2], q[3], 0x5410); wlo.y = prmt(q[2], q[3], 0x7632);
        whi.z = prmt(q[4], q[5], 0x5410); wlo.z = prmt(q[4], q[5], 0x7632);
        whi.w = prmt(q[6], q[7], 0x5410); wlo.w = prmt(q[6], q[7], 0x7632);
        int o = row * 16 + half * 8;
        *(uint4*)&sm[st][0][o] = ahi; *(uint4*)&sm[st][1][o] = alo;
        *(uint4*)&sm[st][2][o] = whi; *(uint4*)&sm[st][3][o] = wlo;
    };

    float acc[2][8][4];
#pragma unroll
    for (int s = 0; s < 2; s++)
#pragma unroll
        for (int nt = 0; nt < 8; nt++)
#pragma unroll
            for (int j = 0; j < 4; j++) acc[s][nt][j] = 0.f;

    uint32_t smb = smem_u32(sm);
    int mt = lane >> 3, rr = lane & 7;   // ldmatrix matrix id, row-in-matrix

    LDG(0); STS(0);
    __syncthreads();

    for (int kk = 0; kk < K16; kk++) {
        if (kk + 1 < K16) LDG(kk + 1);
        int st = kk & 1;
        uint32_t ah[2][4], al[2][4], bh[8][2], bl[8][2];
#pragma unroll
        for (int s = 0; s < 2; s++) {
            // matrices: (m0,k0) (m8,k0) (m0,k8) (m8,k8)
            uint32_t aoff = (uint32_t)(((st * 4 + 0) * 2048 +
                (mi * 32 + s * 16 + (mt & 1) * 8 + rr) * 16 + (mt >> 1) * 8) * 2);
            ldsm4(ah[s], smb + aoff);
            ldsm4(al[s], smb + aoff + 2048 * 2);
        }
#pragma unroll
        for (int np = 0; np < 4; np++) {
            // matrices: (nt,k0) (nt,k8) (nt+1,k0) (nt+1,k8)
            uint32_t boff = (uint32_t)(((st * 4 + 2) * 2048 +
                (nj * 64 + (np * 2 + (mt >> 1)) * 8 + rr) * 16 + (mt & 1) * 8) * 2);
            uint32_t r[4];
            ldsm4(r, smb + boff);
            bh[2 * np][0] = r[0]; bh[2 * np][1] = r[1];
            bh[2 * np + 1][0] = r[2]; bh[2 * np + 1][1] = r[3];
            ldsm4(r, smb + boff + 2048 * 2);
            bl[2 * np][0] = r[0]; bl[2 * np][1] = r[1];
            bl[2 * np + 1][0] = r[2]; bl[2 * np + 1][1] = r[3];
        }
#pragma unroll
        for (int s = 0; s < 2; s++)
#pragma unroll
            for (int nt = 0; nt < 8; nt++) {
                mma16816(acc[s][nt], ah[s], bh[nt][0], bh[nt][1]);
                mma16816(acc[s][nt], ah[s], bl[nt][0], bl[nt][1]);
                mma16816(acc[s][nt], al[s], bh[nt][0], bh[nt][1]);
            }
        if (kk + 1 < K16) STS((kk + 1) & 1);
        __syncthreads();
    }

    // epilogue
#pragma unroll
    for (int s = 0; s < 2; s++) {
        int m = m0 + mi * 32 + s * 16 + (lane >> 2);
#pragma unroll
        for (int nt = 0; nt < 8; nt++) {
            int n = n0 + nj * 64 + nt * 8 + 2 * (lane & 3);
            float b0v = bias[n], b1v = bias[n + 1];
            *(float2*)&C[(ull)m * G4 + n] =
                make_float2(acc[s][nt][0] + b0v, acc[s][nt][1] + b1v);
            *(float2*)&C[(ull)(m + 8) * G4 + n] =
                make_float2(acc[s][nt][2] + b0v, acc[s][nt][3] + b1v);
        }
    }
}

// ============================================================================
// LSTM recurrence (mma.sync split-bf16); pushers write REMOTE fragment layout.
// 8 clusters x 8 CTAs x 256 thr; CTA rank owns units [32r,32r+32).
// ============================================================================
#define RT_CL 8

__global__ __launch_bounds__(256, 1) __cluster_dims__(RT_CL, 1, 1)
void lstm_recur_mma(const float* __restrict__ xg, const float* __restrict__ Whh,
                    uint32_t* __restrict__ hs)
{
    __shared__ ull Bfrag[2][2][512];              // [parity][hi/lo][kt*32 + 4b+cq]
    __shared__ float PRE[8 * 132];                // [b][ri] pitch 132
    __shared__ unsigned short stg2[2][8][32];     // [hi/lo][b][u]
    __shared__ __align__(8) ull bars[2];

    int t = threadIdx.x;
    int w = t >> 5, lane = t & 31;
    uint32_t rank;
    asm("mov.u32 %0, %%cluster_ctarank;" : "=r"(rank));
    int b0 = (blockIdx.x / RT_CL) * 8;

    uint32_t barsb = smem_u32(bars);
    if (t == 0) {
        asm volatile("mbarrier.init.shared.b64 [%0], %1;" :: "r"(barsb),     "r"(256) : "memory");
        asm volatile("mbarrier.init.shared.b64 [%0], %1;" :: "r"(barsb + 8), "r"(256) : "memory");
    }

    // A fragments (hi/lo) in registers
    int r0 = 16 * w + (lane >> 2);
    int k0 = (lane & 3) * 2;
    uint32_t ahi[16][4], alo[16][4];
    {
        int g0 = r0 & 3, u0 = r0 >> 2;
        const float* W0 = Whh + (ull)(256 * g0 + 32 * (int)rank + u0) * H_;
        const float* W1 = W0 + 2 * H_;
#pragma unroll
        for (int kt = 0; kt < 16; kt++) {
            sp2(*(const float2*)(W0 + k0 + 16 * kt),     ahi[kt][0], alo[kt][0]);
            sp2(*(const float2*)(W1 + k0 + 16 * kt),     ahi[kt][1], alo[kt][1]);
            sp2(*(const float2*)(W0 + k0 + 16 * kt + 8), ahi[kt][2], alo[kt][2]);
            sp2(*(const float2*)(W1 + k0 + 16 * kt + 8), ahi[kt][3], alo[kt][3]);
        }
    }
    for (int i = t; i < 1024; i += 256) ((ull*)Bfrag[0])[i] = 0ull;   // h=0 frags
    __syncthreads();
    asm volatile("barrier.cluster.arrive.aligned;" ::: "memory");
    asm volatile("barrier.cluster.wait.aligned;" ::: "memory");

    // pusher identity: tgt CTA, (b, cq); 4 tasks = {hi,lo} x {tile 0,1}
    int tgt = t >> 5;
    int pb = t & 7, pcq = (t >> 3) & 3;
    uint32_t rBf, rBar;
    asm("mapa.shared::cluster.u32 %0, %1, %2;" : "=r"(rBf)  : "r"(smem_u32(Bfrag)), "r"(tgt));
    asm("mapa.shared::cluster.u32 %0, %1, %2;" : "=r"(rBar) : "r"(barsb),           "r"(tgt));

    float c_reg = 0.f;
    int jown = 32 * (int)rank + lane;

    int grow0 = 256 * (r0 & 3) + 32 * (int)rank + (r0 >> 2);
    const float* xp0 = xg + (ull)(b0 + k0) * T_ * G4 + grow0;
    const float* xp1 = xg + (ull)(b0 + k0 + 1) * T_ * G4 + grow0;

    int ph0 = 0, ph1 = 0;

    for (int ts = 0; ts < T_; ts++) {
        int p = ts & 1;
        if (ts) {
            if (p) { mbar_wait_acqc(barsb + 8, ph1); ph1 ^= 1; }
            else   { mbar_wait_acqc(barsb,     ph0); ph0 ^= 1; }
        }
        float x00 = xp0[0], x02 = xp0[2], x01 = xp1[0], x03 = xp1[2];
        xp0 += G4; xp1 += G4;

        // 48 mma, 3 accumulator sets
        float aA[4] = {0, 0, 0, 0}, aB[4] = {0, 0, 0, 0}, aC[4] = {0, 0, 0, 0};
#pragma unroll
        for (int kt = 0; kt < 16; kt++) {
            ull bh = Bfrag[p][0][kt * 32 + lane];
            ull bl = Bfrag[p][1][kt * 32 + lane];
            uint32_t bh0 = (uint32_t)bh, bh1 = (uint32_t)(bh >> 32);
            uint32_t bl0 = (uint32_t)bl, bl1 = (uint32_t)(bl >> 32);
            mma16816(aA, ahi[kt], bh0, bh1);
            mma16816(aB, ahi[kt], bl0, bl1);
            mma16816(aC, alo[kt], bh0, bh1);
        }
        PRE[(k0)     * 132 + r0]     = aA[0] + aB[0] + aC[0] + x00;
        PRE[(k0 + 1) * 132 + r0]     = aA[1] + aB[1] + aC[1] + x01;
        PRE[(k0)     * 132 + r0 + 8] = aA[2] + aB[2] + aC[2] + x02;
        PRE[(k0 + 1) * 132 + r0 + 8] = aA[3] + aB[3] + aC[3] + x03;
        __syncthreads();

        // gates: thread = (u=lane, b=w)
        {
            float4 v = *(const float4*)&PRE[w * 132 + 4 * lane];
            float iv = sigm_f(v.x), fv = sigm_f(v.y), ov = sigm_f(v.w);
            float gv = tanh_f(v.z);
            c_reg = fv * c_reg + iv * gv;
            float h = ov * tanh_f(c_reg);
            __nv_bfloat16 hh = __float2bfloat16(h);
            __nv_bfloat16 hl = __float2bfloat16(h - __bfloat162float(hh));
            unsigned short uh = __bfloat16_as_ushort(hh);
            unsigned short ul = __bfloat16_as_ushort(hl);
            hs[((ull)(b0 + w) * T_ + ts) * H_ + jown] =
                (uint32_t)uh | ((uint32_t)ul << 16);
            stg2[0][w][lane] = uh;
            stg2[1][w][lane] = ul;
        }
        __syncthreads();

        // push direct-fragment u64s into target CTA's Bfrag[p^1]
        {
            uint32_t base = rBf + (uint32_t)((p ^ 1) * 8192);
#pragma unroll
            for (int arr = 0; arr < 2; arr++)
#pragma unroll
                for (int tau = 0; tau < 2; tau++) {
                    uint32_t lo32 = *(const uint32_t*)&stg2[arr][pb][16 * tau + 2 * pcq];
                    uint32_t hi32 = *(const uint32_t*)&stg2[arr][pb][16 * tau + 2 * pcq + 8];
                    ull v = (ull)lo32 | ((ull)hi32 << 32);
                    uint32_t idx = (uint32_t)((2 * (int)rank + tau) * 32 + 4 * pb + pcq);
                    uint32_t dst = base + (uint32_t)(arr * 4096) + idx * 8;
                    asm volatile("st.shared::cluster.u64 [%0], %1;" :: "r"(dst), "l"(v) : "memory");
                }
            asm volatile("mbarrier.arrive.release.cluster.shared::cluster.b64 _, [%0];"
                         :: "r"(rBar + (uint32_t)((p ^ 1) * 8)) : "memory");
        }
    }

    asm volatile("barrier.cluster.arrive.aligned;" ::: "memory");
    asm volatile("barrier.cluster.wait.aligned;" ::: "memory");
}

// ============================================================================
// FC head (reads packed h)
// ============================================================================
__global__ __launch_bounds__(128) void fc_head(
    const uint32_t* __restrict__ hall, const float* __restrict__ W1,
    const float* __restrict__ b1,     const float* __restrict__ W2,
    const float* __restrict__ b2,     float* __restrict__ out)
{
    __shared__ float hl[H_];
    __shared__ float z[128];
    int b = blockIdx.x, t = threadIdx.x;
    hl[t]       = ups(hall[((ull)b * T_ + (T_ - 1)) * H_ + t]);
    hl[t + 128] = ups(hall[((ull)b * T_ + (T_ - 1)) * H_ + t + 128]);
    __syncthreads();
    float acc = b1[t];
    const float* ww = W1 + t * H_;
#pragma unroll 8
    for (int k = 0; k < H_; k++) acc += ww[k] * hl[k];
    z[t] = fmaxf(acc, 0.f);
    __syncthreads();
    if (t < NC_) {
        float a2 = b2[t];
        const float* w2 = W2 + t * 128;
#pragma unroll 8
        for (int k = 0; k < 128; k++) a2 += w2[k] * z[k];
        out[b * NC_ + t] = a2;
    }
}

// ============================================================================
extern "C" void kernel_launch(void* const* d_in, const int* in_sizes, int n_in,
                              void* d_out, int out_size)
{
    const float* x    = (const float*)d_in[0];
    const float* Wih0 = (const float*)d_in[1];
    const float* Whh0 = (const float*)d_in[2];
    const float* b0   = (const float*)d_in[3];
    const float* Wih1 = (const float*)d_in[4];
    const float* Whh1 = (const float*)d_in[5];
    const float* b1   = (const float*)d_in[6];
    const float* Wih2 = (const float*)d_in[7];
    const float* Whh2 = (const float*)d_in[8];
    const float* b2   = (const float*)d_in[9];
    const float* W1   = (const float*)d_in[10];
    const float* bfc1 = (const float*)d_in[11];
    const float* W2   = (const float*)d_in[12];
    const float* bfc2 = (const float*)d_in[13];
    float* out = (float*)d_out;

    float* xg; uint32_t *as, *hs1, *hs2, *ws;
    cudaGetSymbolAddress((void**)&xg,  g_xg);
    cudaGetSymbolAddress((void**)&as,  g_as);
    cudaGetSymbolAddress((void**)&hs1, g_hs1);
    cudaGetSymbolAddress((void**)&hs2, g_hs2);
    cudaGetSymbolAddress((void**)&ws,  g_ws);

    dim3 ggrd(G4 / 128, (B_ * T_) / 128);   // (8, 256)
    int rgrid = (B_ / 8) * RT_CL;           // 64 CTAs
    int nx  = B_ * T_ * IN_ / 4;
    int nw0 = G4 * IN_ / 4;
    int nwh = G4 * H_ / 4;

    // layer 0
    split_ps<<<(nx + 255) / 256, 256>>>(x, as, nx);
    split_ps<<<(nw0 + 255) / 256, 256>>>(Wih0, ws, nw0);
    gemm_tc<<<ggrd, 256>>>(as, ws, b0, xg, IN_);
    lstm_recur_mma<<<rgrid, 256>>>(xg, Whh0, hs1);
    // layer 1
    split_ps<<<(nwh + 255) / 256, 256>>>(Wih1, ws, nwh);
    gemm_tc<<<ggrd, 256>>>(hs1, ws, b1, xg, H_);
    lstm_recur_mma<<<rgrid, 256>>>(xg, Whh1, hs2);
    // layer 2
    split_ps<<<(nwh + 255) / 256, 256>>>(Wih2, ws, nwh);
    gemm_tc<<<ggrd, 256>>>(hs2, ws, b2, xg, H_);
    lstm_recur_mma<<<rgrid, 256>>>(xg, Whh2, hs1);
    // head
    fc_head<<<B_, 128>>>(hs1, W1, bfc1, W2, bfc2, out);
}